// round 1
// baseline (speedup 1.0000x reference)
#include <cuda_runtime.h>
#include <math.h>
#include <float.h>

#define SEQ 1024
#define DMODEL 4096
#define NH 32
#define HD 128
#define HB 102            /* heavy budget  = int(0.1*1024) */
#define RB 102            /* recent budget = int(0.1*1024) */
#define NEGF (-3.402823466e38f)

// ---------------- static device scratch (no allocations allowed) ----------------
__device__ float    g_Q[SEQ * DMODEL];
__device__ float    g_K[SEQ * DMODEL];
__device__ float    g_V[SEQ * DMODEL];
__device__ float    g_P[(size_t)NH * SEQ * SEQ];   // logits, then probs (in place)
__device__ unsigned g_M[NH * SEQ * (SEQ / 32)];    // heavy-hitter mask bits
__device__ float    g_AO[SEQ * DMODEL];            // attention output [s, h*128+d]

// ---------------- fp32 tiled GEMM, C = A * B^T (both row-major) ----------------
// 128x128 tile, BK=16, 256 threads, 8x8 per thread.
template <bool MASKED>
__device__ __forceinline__ void sgemm_nt_dev(
    const float* __restrict__ A, const float* __restrict__ B, float* __restrict__ C,
    int K, int lda, int ldb, int ldc, float scale)
{
    __shared__ float As[16][128];
    __shared__ float Bs[16][128];
    const int tid = threadIdx.x;
    const int m0 = blockIdx.y * 128;
    const int n0 = blockIdx.x * 128;
    const int lrow = tid >> 2;          // 0..63
    const int lcol = (tid & 3) << 2;    // 0,4,8,12
    const float* Ag = A + (size_t)(m0 + lrow) * lda + lcol;
    const float* Bg = B + (size_t)(n0 + lrow) * ldb + lcol;
    const int ty = tid >> 4, tx = tid & 15;

    float acc[8][8];
#pragma unroll
    for (int i = 0; i < 8; i++)
#pragma unroll
        for (int j = 0; j < 8; j++) acc[i][j] = 0.f;

    for (int k0 = 0; k0 < K; k0 += 16) {
        float4 a0 = *(const float4*)(Ag + k0);
        float4 a1 = *(const float4*)(Ag + (size_t)64 * lda + k0);
        float4 b0 = *(const float4*)(Bg + k0);
        float4 b1 = *(const float4*)(Bg + (size_t)64 * ldb + k0);
        __syncthreads();
        As[lcol + 0][lrow] = a0.x; As[lcol + 1][lrow] = a0.y;
        As[lcol + 2][lrow] = a0.z; As[lcol + 3][lrow] = a0.w;
        As[lcol + 0][lrow + 64] = a1.x; As[lcol + 1][lrow + 64] = a1.y;
        As[lcol + 2][lrow + 64] = a1.z; As[lcol + 3][lrow + 64] = a1.w;
        Bs[lcol + 0][lrow] = b0.x; Bs[lcol + 1][lrow] = b0.y;
        Bs[lcol + 2][lrow] = b0.z; Bs[lcol + 3][lrow] = b0.w;
        Bs[lcol + 0][lrow + 64] = b1.x; Bs[lcol + 1][lrow + 64] = b1.y;
        Bs[lcol + 2][lrow + 64] = b1.z; Bs[lcol + 3][lrow + 64] = b1.w;
        __syncthreads();
#pragma unroll
        for (int kk = 0; kk < 16; kk++) {
            float4 av0 = *(const float4*)&As[kk][ty * 8];
            float4 av1 = *(const float4*)&As[kk][ty * 8 + 4];
            float4 bv0 = *(const float4*)&Bs[kk][tx * 8];
            float4 bv1 = *(const float4*)&Bs[kk][tx * 8 + 4];
            float ar[8] = {av0.x, av0.y, av0.z, av0.w, av1.x, av1.y, av1.z, av1.w};
            float br[8] = {bv0.x, bv0.y, bv0.z, bv0.w, bv1.x, bv1.y, bv1.z, bv1.w};
#pragma unroll
            for (int i = 0; i < 8; i++)
#pragma unroll
                for (int j = 0; j < 8; j++) acc[i][j] += ar[i] * br[j];
        }
    }
#pragma unroll
    for (int i = 0; i < 8; i++) {
        const int mi = m0 + ty * 8 + i;
#pragma unroll
        for (int j = 0; j < 8; j++) {
            const int nj = n0 + tx * 8 + j;
            float v = acc[i][j] * scale;
            if (MASKED && nj > mi) v = NEGF;
            C[(size_t)mi * ldc + nj] = v;
        }
    }
}

// ---------------- stage 1: Q/K/V = X @ W^T ----------------
__global__ __launch_bounds__(256) void qkv_kernel(
    const float* __restrict__ X, const float* __restrict__ Wq,
    const float* __restrict__ Wk, const float* __restrict__ Wv)
{
    const float* W = (blockIdx.z == 0) ? Wq : (blockIdx.z == 1) ? Wk : Wv;
    float* O = (blockIdx.z == 0) ? g_Q : (blockIdx.z == 1) ? g_K : g_V;
    sgemm_nt_dev<false>(X, W, O, DMODEL, DMODEL, DMODEL, DMODEL, 1.0f);
}

// ---------------- stage 2: RoPE in place on Q and K ----------------
__global__ void rope_kernel()
{
    int idx = blockIdx.x * blockDim.x + threadIdx.x;   // [0, 1024*32*64)
    float* buf = blockIdx.y ? g_K : g_Q;
    int p = idx & 63;
    int h = (idx >> 6) & 31;
    int s = idx >> 11;
    float inv = 1.0f / powf(10000.0f, (float)(2 * p) * (1.0f / 128.0f));
    float ang = (float)s * inv;
    float sn, c;
    sincosf(ang, &sn, &c);
    size_t b = (size_t)s * DMODEL + h * HD + p;
    float q0 = buf[b], q1 = buf[b + 64];
    buf[b]      = q0 * c - q1 * sn;
    buf[b + 64] = q1 * c + q0 * sn;
}

// ---------------- stage 3: causal logits per head ----------------
__global__ __launch_bounds__(256) void qk_kernel()
{
    const int h = blockIdx.z;
    if (blockIdx.x > blockIdx.y) return;   // tile fully above diagonal: skip
    sgemm_nt_dev<true>(g_Q + h * HD, g_K + h * HD, g_P + (size_t)h * SEQ * SEQ,
                       HD, DMODEL, DMODEL, SEQ, 0.08838834764831845f /* 1/sqrt(128) */);
}

// ---------------- stage 3b: row softmax in place (probs P0) ----------------
__global__ __launch_bounds__(256) void softmax_kernel()
{
    const int i = blockIdx.x, h = blockIdx.y;
    float* row = g_P + (size_t)h * SEQ * SEQ + (size_t)i * SEQ;
    const int n = i + 1;
    const int tid = threadIdx.x;
    const int lane = tid & 31, wid = tid >> 5;
    __shared__ float red[16];

    float m = -FLT_MAX;
    for (int j = tid; j < n; j += 256) m = fmaxf(m, row[j]);
#pragma unroll
    for (int o = 16; o; o >>= 1) m = fmaxf(m, __shfl_xor_sync(0xffffffffu, m, o));
    if (lane == 0) red[wid] = m;
    __syncthreads();
    m = red[0];
#pragma unroll
    for (int w = 1; w < 8; w++) m = fmaxf(m, red[w]);

    float s = 0.f;
    for (int j = tid; j < n; j += 256) s += expf(row[j] - m);
#pragma unroll
    for (int o = 16; o; o >>= 1) s += __shfl_xor_sync(0xffffffffu, s, o);
    if (lane == 0) red[8 + wid] = s;
    __syncthreads();
    float tot = 0.f;
#pragma unroll
    for (int w = 0; w < 8; w++) tot += red[8 + w];
    const float invs = 1.0f / tot;

    for (int j = tid; j < SEQ; j += 256)
        row[j] = (j < n) ? expf(row[j] - m) * invs : 0.f;
}

// ---------------- stage 4: sequential H2O scan, one warp per head ----------------
__global__ void scan_kernel()
{
    const int h = blockIdx.x;
    const int lane = threadIdx.x;
    __shared__ float acc[SEQ];
    __shared__ int   lst[128];
    __shared__ float skey[128];
    __shared__ unsigned mw[32];
    const float* P = g_P + (size_t)h * SEQ * SEQ;
    unsigned* MB = g_M + h * SEQ * (SEQ / 32);

    for (int j = lane; j < SEQ; j += 32) acc[j] = 0.f;
    __syncwarp();
    // acc0[j] = sum_{i<HB} P0[i,j] for j<HB  (P0 is exactly 0 above the diagonal)
    for (int j = lane; j < HB; j += 32) {
        float s = 0.f;
        for (int i = 0; i < HB; i++) s += P[(size_t)i * SEQ + j];
        acc[j] = s;
    }
    for (int p = lane; p < HB; p += 32) lst[p] = p;
    int cnt = HB;
    __syncwarp();

    for (int t = HB; t < SEQ; t++) {
        const float* Prow = P + (size_t)t * SEQ;
        // L2 prefetch of the row we gather at the end of this iteration
        asm volatile("prefetch.global.L2 [%0];" :: "l"(Prow + lane * 32));

        for (int p = lane; p < cnt; p += 32) skey[p] = acc[lst[p]];
        __syncwarp();

        const int r = cnt - (HB - 1);   // how many to drop from the top-k
        for (int rep = 0; rep < r; rep++) {
            // find min by (value asc, index desc)  == drop from top_k keeping
            // the lowest-index entry among value ties (jax.lax.top_k stability)
            float bv = FLT_MAX; int bidx = -1; int bpos = 0;
            for (int p = lane; p < cnt; p += 32) {
                float v = skey[p]; int ix = lst[p];
                if (v < bv || (v == bv && ix > bidx)) { bv = v; bidx = ix; bpos = p; }
            }
#pragma unroll
            for (int o = 16; o; o >>= 1) {
                float ov = __shfl_down_sync(0xffffffffu, bv, o);
                int   oi = __shfl_down_sync(0xffffffffu, bidx, o);
                int   op = __shfl_down_sync(0xffffffffu, bpos, o);
                if (ov < bv || (ov == bv && oi > bidx)) { bv = ov; bidx = oi; bpos = op; }
            }
            bidx = __shfl_sync(0xffffffffu, bidx, 0);
            bpos = __shfl_sync(0xffffffffu, bpos, 0);
            if (bidx >= 4) {            // really evicted: zero acc, delete slot
                if (lane == 0) {
                    acc[bidx] = 0.f;
                    lst[bpos]  = lst[cnt - 1];
                    skey[bpos] = skey[cnt - 1];
                }
                cnt--;
            } else {                    // cols 0..3 always stay in the mask
                if (lane == 0) skey[bpos] = FLT_MAX;
            }
            __syncwarp();
        }
        if (lane == 0) lst[cnt] = t;    // current token always in mask
        cnt++;
        mw[lane] = 0u;
        __syncwarp();
        for (int p = lane; p < cnt; p += 32) {
            int ix = lst[p];
            acc[ix] += Prow[ix];        // acc = (acc + prob_row) * m
            atomicOr(&mw[ix >> 5], 1u << (ix & 31));
        }
        __syncwarp();
        MB[t * 32 + lane] = mw[lane];
        __syncwarp();
    }
}

// ---------------- stage 5: masked renormalized softmax + P @ V ----------------
__global__ __launch_bounds__(128) void pv_kernel()
{
    const int s = blockIdx.x, h = blockIdx.y;
    const int tid = threadIdx.x;
    const int lane = tid & 31, wid = tid >> 5;
    __shared__ float pv[224];
    __shared__ int   pj[224];
    __shared__ int   wbase[4];
    __shared__ float wsum[4];
    __shared__ int   s_cnt;
    __shared__ float s_sum;
    const float* Prow = g_P + (size_t)h * SEQ * SEQ + (size_t)s * SEQ;
    const unsigned* mb = g_M + (h * SEQ + s) * (SEQ / 32);

    float pr[8]; bool al[8];
    int c = 0; float lsum = 0.f;
    const int j0 = tid * 8;
#pragma unroll
    for (int u = 0; u < 8; u++) {
        const int j = j0 + u;
        bool a;
        if (s < HB) a = (j <= s);                       // rows < HB: recent covers all causal
        else        a = (j <= s) && ((j + RB >= s) || ((mb[j >> 5] >> (j & 31)) & 1u));
        float val = a ? Prow[j] : 0.f;
        al[u] = a; pr[u] = val;
        if (a) { c++; lsum += val; }
    }
    // deterministic compaction: warp scan + cross-warp offsets
    int inc = c;
#pragma unroll
    for (int o = 1; o < 32; o <<= 1) {
        int v = __shfl_up_sync(0xffffffffu, inc, o);
        if (lane >= o) inc += v;
    }
    float ws = lsum;
#pragma unroll
    for (int o = 16; o; o >>= 1) ws += __shfl_xor_sync(0xffffffffu, ws, o);
    if (lane == 31) wbase[wid] = inc;
    if (lane == 0)  wsum[wid] = ws;
    __syncthreads();
    if (tid == 0) {
        int tot = 0;
#pragma unroll
        for (int w = 0; w < 4; w++) { int b = wbase[w]; wbase[w] = tot; tot += b; }
        s_cnt = tot;
        s_sum = wsum[0] + wsum[1] + wsum[2] + wsum[3];
    }
    __syncthreads();
    int k = wbase[wid] + inc - c;
#pragma unroll
    for (int u = 0; u < 8; u++)
        if (al[u]) { pv[k] = pr[u]; pj[k] = j0 + u; k++; }
    __syncthreads();

    const int cnt = s_cnt;
    const float inv = 1.0f / s_sum;   // renormalize P0 over allowed set == 2nd softmax
    const float* Vh = g_V + h * HD + tid;
    float acc = 0.f;
    int m2 = 0;
    for (; m2 + 4 <= cnt; m2 += 4) {
        acc += pv[m2 + 0] * Vh[(size_t)pj[m2 + 0] * DMODEL];
        acc += pv[m2 + 1] * Vh[(size_t)pj[m2 + 1] * DMODEL];
        acc += pv[m2 + 2] * Vh[(size_t)pj[m2 + 2] * DMODEL];
        acc += pv[m2 + 3] * Vh[(size_t)pj[m2 + 3] * DMODEL];
    }
    for (; m2 < cnt; m2++) acc += pv[m2] * Vh[(size_t)pj[m2] * DMODEL];
    g_AO[(size_t)s * DMODEL + h * HD + tid] = acc * inv;
}

// ---------------- stage 6: output projection ----------------
__global__ __launch_bounds__(256) void oproj_kernel(
    const float* __restrict__ Wo, float* __restrict__ out)
{
    sgemm_nt_dev<false>(g_AO, Wo, out, DMODEL, DMODEL, DMODEL, DMODEL, 1.0f);
}

// ---------------- launch ----------------
extern "C" void kernel_launch(void* const* d_in, const int* in_sizes, int n_in,
                              void* d_out, int out_size)
{
    const float* X  = (const float*)d_in[0];
    /* d_in[1] = attention_mask (pure causal; reconstructed analytically) */
    const float* Wq = (const float*)d_in[2];
    const float* Wk = (const float*)d_in[3];
    const float* Wv = (const float*)d_in[4];
    const float* Wo = (const float*)d_in[5];
    float* out = (float*)d_out;

    qkv_kernel<<<dim3(DMODEL / 128, SEQ / 128, 3), 256>>>(X, Wq, Wk, Wv);
    rope_kernel<<<dim3((SEQ * NH * 64) / 256, 2), 256>>>();
    qk_kernel<<<dim3(SEQ / 128, SEQ / 128, NH), 256>>>();
    softmax_kernel<<<dim3(SEQ, NH), 256>>>();
    scan_kernel<<<NH, 32>>>();
    pv_kernel<<<dim3(SEQ, NH), 128>>>();
    oproj_kernel<<<dim3(DMODEL / 128, SEQ / 128), 256>>>(Wo, out);
}

// round 3
// speedup vs baseline: 1.5548x; 1.5548x over previous
#include <cuda_runtime.h>
#include <cuda_bf16.h>
#include <math.h>
#include <float.h>
#include <stdint.h>

#define SEQ 1024
#define DMODEL 4096
#define NH 32
#define HD 128
#define HB 102
#define RB 102

// ======================= static device scratch =======================
__device__ __align__(256) float g_Q[SEQ * DMODEL];
__device__ __align__(256) float g_K[SEQ * DMODEL];
__device__ __align__(256) float g_V[SEQ * DMODEL];
__device__ __align__(256) float g_P[(size_t)NH * SEQ * SEQ];
__device__ unsigned g_M[NH * SEQ * (SEQ / 32)];
__device__ __align__(256) __nv_bfloat16 g_Xhi[SEQ * DMODEL], g_Xlo[SEQ * DMODEL];
__device__ __align__(256) __nv_bfloat16 g_Whi[4][DMODEL * DMODEL];
__device__ __align__(256) __nv_bfloat16 g_Wlo[4][DMODEL * DMODEL];
__device__ __align__(256) __nv_bfloat16 g_Qhi[SEQ * DMODEL], g_Qlo[SEQ * DMODEL];
__device__ __align__(256) __nv_bfloat16 g_Khi[SEQ * DMODEL], g_Klo[SEQ * DMODEL];
__device__ __align__(256) __nv_bfloat16 g_AOhi[SEQ * DMODEL], g_AOlo[SEQ * DMODEL];

// ======================= helpers =======================
__device__ __forceinline__ uint32_t smem_u32(const void* p) {
    uint32_t a;
    asm("{ .reg .u64 t; cvta.to.shared.u64 t, %1; cvt.u32.u64 %0, t; }" : "=r"(a) : "l"(p));
    return a;
}
__device__ __forceinline__ void cp16(uint32_t dst, const void* src) {
    asm volatile("cp.async.cg.shared.global [%0], [%1], 16;" :: "r"(dst), "l"(src));
}
__device__ __forceinline__ void cp_commit() { asm volatile("cp.async.commit_group;" ::: "memory"); }
__device__ __forceinline__ void cp_wait1() { asm volatile("cp.async.wait_group 1;" ::: "memory"); }
__device__ __forceinline__ void cp_wait0() { asm volatile("cp.async.wait_group 0;" ::: "memory"); }

__device__ __forceinline__ void ldsm4(uint32_t* r, uint32_t addr) {
    asm volatile("ldmatrix.sync.aligned.m8n8.x4.shared.b16 {%0,%1,%2,%3}, [%4];"
        : "=r"(r[0]), "=r"(r[1]), "=r"(r[2]), "=r"(r[3]) : "r"(addr));
}
__device__ __forceinline__ void mma_bf16(float* c, const uint32_t* a, uint32_t b0, uint32_t b1) {
    asm volatile("mma.sync.aligned.m16n8k16.row.col.f32.bf16.bf16.f32 "
        "{%0,%1,%2,%3}, {%4,%5,%6,%7}, {%8,%9}, {%0,%1,%2,%3};"
        : "+f"(c[0]), "+f"(c[1]), "+f"(c[2]), "+f"(c[3])
        : "r"(a[0]), "r"(a[1]), "r"(a[2]), "r"(a[3]), "r"(b0), "r"(b1));
}

// ======================= split-bf16 HMMA GEMM core =======================
// C[128 x 128] = (Ahi+Alo)[128 x K] * (Bhi+Blo)[128 x K]^T   (lo*lo dropped)
// BK = 64, double-buffered cp.async. 256 threads, warp grid 4(M) x 2(N).
#define ROWB 144                      /* 64 bf16 = 128B + 16B pad (conflict-free ldsm) */
#define AMAT (128 * ROWB)             /* one 128x64 bf16 matrix slab */
#define STAGE (4 * AMAT)              /* Ahi | Alo | Bhi | Blo */
#define MM_SMEM (2 * STAGE)           /* 147456 B */

__device__ __forceinline__ void ld_stage(
    uint32_t st, const __nv_bfloat16* Ahi, const __nv_bfloat16* Alo,
    const __nv_bfloat16* Bhi, const __nv_bfloat16* Blo,
    int lda, int ldb, int k0, int tid)
{
#pragma unroll
    for (int it = 0; it < 4; it++) {
        int idx = it * 256 + tid;           // 1024 granules of 16B per matrix
        int row = idx >> 3, g = idx & 7;
        uint32_t off = row * ROWB + g * 16;
        size_t sa = (size_t)row * lda + k0 + g * 8;
        size_t sbv = (size_t)row * ldb + k0 + g * 8;
        cp16(st + off, Ahi + sa);
        cp16(st + AMAT + off, Alo + sa);
        cp16(st + 2 * AMAT + off, Bhi + sbv);
        cp16(st + 3 * AMAT + off, Blo + sbv);
    }
}

__device__ __forceinline__ void mm_hmma(
    const __nv_bfloat16* __restrict__ Ahi, const __nv_bfloat16* __restrict__ Alo, int lda,
    const __nv_bfloat16* __restrict__ Bhi, const __nv_bfloat16* __restrict__ Blo, int ldb,
    float* __restrict__ C, int ldc, int nk, float scale)
{
    extern __shared__ char smem[];
    const uint32_t sb = smem_u32(smem);
    const int tid = threadIdx.x, lane = tid & 31, wid = tid >> 5;
    const int wm = wid & 3, wn = wid >> 2;

    float c[2][8][4];
#pragma unroll
    for (int i = 0; i < 2; i++)
#pragma unroll
        for (int j = 0; j < 8; j++)
#pragma unroll
            for (int q = 0; q < 4; q++) c[i][j][q] = 0.f;

    ld_stage(sb, Ahi, Alo, Bhi, Blo, lda, ldb, 0, tid); cp_commit();
    ld_stage(sb + STAGE, Ahi, Alo, Bhi, Blo, lda, ldb, 64, tid); cp_commit();

    for (int ck = 0; ck < nk; ck++) {
        if (ck == nk - 1) cp_wait0(); else cp_wait1();
        __syncthreads();
        const uint32_t st = sb + (ck & 1) * STAGE;
#pragma unroll
        for (int k16 = 0; k16 < 4; k16++) {
            uint32_t ah[2][4], al[2][4];
#pragma unroll
            for (int i = 0; i < 2; i++) {
                uint32_t ad = st + (uint32_t)((wm * 32 + i * 16 + (lane & 15)) * ROWB
                                              + k16 * 32 + ((lane >> 4) << 4));
                ldsm4(ah[i], ad);
                ldsm4(al[i], ad + AMAT);
            }
            uint32_t bh[4][4], bl[4][4];
#pragma unroll
            for (int j4 = 0; j4 < 4; j4++) {
                uint32_t bd = st + 2 * AMAT
                    + (uint32_t)((wn * 64 + j4 * 16 + ((lane >> 4) << 3) + (lane & 7)) * ROWB
                                 + k16 * 32 + (((lane >> 3) & 1) << 4));
                ldsm4(bh[j4], bd);
                ldsm4(bl[j4], bd + AMAT);
            }
#pragma unroll
            for (int i = 0; i < 2; i++)
#pragma unroll
                for (int j4 = 0; j4 < 4; j4++) {
                    mma_bf16(c[i][2 * j4],     ah[i], bh[j4][0], bh[j4][1]);
                    mma_bf16(c[i][2 * j4],     ah[i], bl[j4][0], bl[j4][1]);
                    mma_bf16(c[i][2 * j4],     al[i], bh[j4][0], bh[j4][1]);
                    mma_bf16(c[i][2 * j4 + 1], ah[i], bh[j4][2], bh[j4][3]);
                    mma_bf16(c[i][2 * j4 + 1], ah[i], bl[j4][2], bl[j4][3]);
                    mma_bf16(c[i][2 * j4 + 1], al[i], bh[j4][2], bh[j4][3]);
                }
        }
        __syncthreads();
        if (ck + 2 < nk) {
            ld_stage(st, Ahi, Alo, Bhi, Blo, lda, ldb, (ck + 2) * 64, tid);
            cp_commit();
        }
    }

    const int r0 = wm * 32 + (lane >> 2);
    const int c0 = wn * 64 + (lane & 3) * 2;
#pragma unroll
    for (int i = 0; i < 2; i++)
#pragma unroll
        for (int j = 0; j < 8; j++) {
            float2 v0 = { c[i][j][0] * scale, c[i][j][1] * scale };
            float2 v1 = { c[i][j][2] * scale, c[i][j][3] * scale };
            *(float2*)&C[(size_t)(r0 + i * 16) * ldc + c0 + j * 8] = v0;
            *(float2*)&C[(size_t)(r0 + i * 16 + 8) * ldc + c0 + j * 8] = v1;
        }
}

// ======================= conversion fp32 -> bf16 hi/lo =======================
__global__ __launch_bounds__(256) void cvt_kernel(const float* __restrict__ src, int n4, int which)
{
    __nv_bfloat16 *hi, *lo;
    switch (which) {
        case 0: hi = g_Xhi;    lo = g_Xlo;    break;
        case 1: hi = g_Whi[0]; lo = g_Wlo[0]; break;
        case 2: hi = g_Whi[1]; lo = g_Wlo[1]; break;
        case 3: hi = g_Whi[2]; lo = g_Wlo[2]; break;
        default: hi = g_Whi[3]; lo = g_Wlo[3]; break;
    }
    int i = blockIdx.x * 256 + threadIdx.x;
    if (i >= n4) return;
    float4 v = ((const float4*)src)[i];
    __nv_bfloat16 h0 = __float2bfloat16(v.x), h1 = __float2bfloat16(v.y);
    __nv_bfloat16 h2 = __float2bfloat16(v.z), h3 = __float2bfloat16(v.w);
    __nv_bfloat162 H01; H01.x = h0; H01.y = h1;
    __nv_bfloat162 H23; H23.x = h2; H23.y = h3;
    __nv_bfloat162 L01, L23;
    L01.x = __float2bfloat16(v.x - __bfloat162float(h0));
    L01.y = __float2bfloat16(v.y - __bfloat162float(h1));
    L23.x = __float2bfloat16(v.z - __bfloat162float(h2));
    L23.y = __float2bfloat16(v.w - __bfloat162float(h3));
    *(__nv_bfloat162*)(hi + 4 * (size_t)i)     = H01;
    *(__nv_bfloat162*)(hi + 4 * (size_t)i + 2) = H23;
    *(__nv_bfloat162*)(lo + 4 * (size_t)i)     = L01;
    *(__nv_bfloat162*)(lo + 4 * (size_t)i + 2) = L23;
}

// ======================= GEMM wrappers =======================
__global__ __launch_bounds__(256, 1) void mm_qkv_kernel()
{
    const int z = blockIdx.z;
    const int m0 = blockIdx.y * 128, n0 = blockIdx.x * 128;
    float* O = (z == 0) ? g_Q : (z == 1) ? g_K : g_V;
    mm_hmma(g_Xhi + (size_t)m0 * DMODEL, g_Xlo + (size_t)m0 * DMODEL, DMODEL,
            g_Whi[z] + (size_t)n0 * DMODEL, g_Wlo[z] + (size_t)n0 * DMODEL, DMODEL,
            O + (size_t)m0 * DMODEL + n0, DMODEL, DMODEL / 64, 1.0f);
}

__global__ __launch_bounds__(256, 1) void mm_o_kernel(float* __restrict__ out)
{
    const int m0 = blockIdx.y * 128, n0 = blockIdx.x * 128;
    mm_hmma(g_AOhi + (size_t)m0 * DMODEL, g_AOlo + (size_t)m0 * DMODEL, DMODEL,
            g_Whi[3] + (size_t)n0 * DMODEL, g_Wlo[3] + (size_t)n0 * DMODEL, DMODEL,
            out + (size_t)m0 * DMODEL + n0, DMODEL, DMODEL / 64, 1.0f);
}

__global__ __launch_bounds__(256, 1) void mm_qk_kernel()
{
    const int h = blockIdx.z;
    const int m0 = blockIdx.y * 128, n0 = blockIdx.x * 128;
    if (blockIdx.x > blockIdx.y) return;   // tile entirely above diagonal: never read
    mm_hmma(g_Qhi + (size_t)m0 * DMODEL + h * HD, g_Qlo + (size_t)m0 * DMODEL + h * HD, DMODEL,
            g_Khi + (size_t)n0 * DMODEL + h * HD, g_Klo + (size_t)n0 * DMODEL + h * HD, DMODEL,
            g_P + (size_t)h * SEQ * SEQ + (size_t)m0 * SEQ + n0, SEQ,
            HD / 64, 0.08838834764831845f);
}

// ======================= RoPE: fp32 Q/K -> roped bf16 hi/lo =======================
__global__ void rope_kernel()
{
    int idx = blockIdx.x * blockDim.x + threadIdx.x;   // [0, 1024*32*64)
    const float* src = blockIdx.y ? g_K : g_Q;
    __nv_bfloat16* hi = blockIdx.y ? g_Khi : g_Qhi;
    __nv_bfloat16* lo = blockIdx.y ? g_Klo : g_Qlo;
    int p = idx & 63;
    int h = (idx >> 6) & 31;
    int s = idx >> 11;
    float inv = 1.0f / powf(10000.0f, (float)(2 * p) * (1.0f / 128.0f));
    float ang = (float)s * inv;
    float sn, c;
    sincosf(ang, &sn, &c);
    size_t b = (size_t)s * DMODEL + h * HD + p;
    float q0 = src[b], q1 = src[b + 64];
    float r0 = q0 * c - q1 * sn;
    float r1 = q1 * c + q0 * sn;
    __nv_bfloat16 h0 = __float2bfloat16(r0);
    __nv_bfloat16 h1 = __float2bfloat16(r1);
    hi[b] = h0;      lo[b]      = __float2bfloat16(r0 - __bfloat162float(h0));
    hi[b + 64] = h1; lo[b + 64] = __float2bfloat16(r1 - __bfloat162float(h1));
}

// ======================= softmax (probs P0, zero above diagonal) =======================
__global__ __launch_bounds__(256) void softmax_kernel()
{
    const int i = blockIdx.x, h = blockIdx.y;
    float* row = g_P + (size_t)h * SEQ * SEQ + (size_t)i * SEQ;
    const int n = i + 1;
    const int tid = threadIdx.x;
    const int lane = tid & 31, wid = tid >> 5;
    __shared__ float red[16];

    float m = -FLT_MAX;
    for (int j = tid; j < n; j += 256) m = fmaxf(m, row[j]);
#pragma unroll
    for (int o = 16; o; o >>= 1) m = fmaxf(m, __shfl_xor_sync(0xffffffffu, m, o));
    if (lane == 0) red[wid] = m;
    __syncthreads();
    m = red[0];
#pragma unroll
    for (int w = 1; w < 8; w++) m = fmaxf(m, red[w]);

    float s = 0.f;
    for (int j = tid; j < n; j += 256) s += expf(row[j] - m);
#pragma unroll
    for (int o = 16; o; o >>= 1) s += __shfl_xor_sync(0xffffffffu, s, o);
    if (lane == 0) red[8 + wid] = s;
    __syncthreads();
    float tot = 0.f;
#pragma unroll
    for (int w = 0; w < 8; w++) tot += red[8 + w];
    const float invs = 1.0f / tot;

    for (int j = tid; j < SEQ; j += 256)
        row[j] = (j < n) ? expf(row[j] - m) * invs : 0.f;
}

// ======================= H2O sequential scan, one warp per head =======================
__global__ void scan_kernel()
{
    const int h = blockIdx.x;
    const int lane = threadIdx.x;
    __shared__ float acc[SEQ];
    __shared__ int   lst[128];
    __shared__ float skey[128];
    __shared__ unsigned mw[32];
    const float* P = g_P + (size_t)h * SEQ * SEQ;
    unsigned* MB = g_M + h * SEQ * (SEQ / 32);

    for (int j = lane; j < SEQ; j += 32) acc[j] = 0.f;
    __syncwarp();
    for (int j = lane; j < HB; j += 32) {
        float s = 0.f;
        for (int i = 0; i < HB; i++) s += P[(size_t)i * SEQ + j];
        acc[j] = s;
    }
    for (int p = lane; p < HB; p += 32) lst[p] = p;
    int cnt = HB;
    __syncwarp();

    for (int t = HB; t < SEQ; t++) {
        const float* Prow = P + (size_t)t * SEQ;
        for (int p = lane; p < cnt; p += 32) {
            const float* a = Prow + lst[p];
            asm volatile("prefetch.global.L2 [%0];" :: "l"(a));
        }
        if (lane == 0) {
            const float* a = Prow + t;
            asm volatile("prefetch.global.L2 [%0];" :: "l"(a));
        }

        for (int p = lane; p < cnt; p += 32) skey[p] = acc[lst[p]];
        __syncwarp();

        const int r = cnt - (HB - 1);
        for (int rep = 0; rep < r; rep++) {
            float bv = FLT_MAX; int bidx = -1; int bpos = 0;
            for (int p = lane; p < cnt; p += 32) {
                float v = skey[p]; int ix = lst[p];
                if (v < bv || (v == bv && ix > bidx)) { bv = v; bidx = ix; bpos = p; }
            }
#pragma unroll
            for (int o = 16; o; o >>= 1) {
                float ov = __shfl_down_sync(0xffffffffu, bv, o);
                int   oi = __shfl_down_sync(0xffffffffu, bidx, o);
                int   op = __shfl_down_sync(0xffffffffu, bpos, o);
                if (ov < bv || (ov == bv && oi > bidx)) { bv = ov; bidx = oi; bpos = op; }
            }
            bidx = __shfl_sync(0xffffffffu, bidx, 0);
            bpos = __shfl_sync(0xffffffffu, bpos, 0);
            if (bidx >= 4) {
                if (lane == 0) {
                    acc[bidx] = 0.f;
                    lst[bpos]  = lst[cnt - 1];
                    skey[bpos] = skey[cnt - 1];
                }
                cnt--;
            } else {
                if (lane == 0) skey[bpos] = FLT_MAX;
            }
            __syncwarp();
        }
        if (lane == 0) lst[cnt] = t;
        cnt++;
        mw[lane] = 0u;
        __syncwarp();
        for (int p = lane; p < cnt; p += 32) {
            int ix = lst[p];
            acc[ix] += Prow[ix];
            atomicOr(&mw[ix >> 5], 1u << (ix & 31));
        }
        __syncwarp();
        MB[t * 32 + lane] = mw[lane];
        __syncwarp();
    }
}

// ======================= masked renorm softmax + P@V (writes AO hi/lo) =======================
__global__ __launch_bounds__(128) void pv_kernel()
{
    const int s = blockIdx.x, h = blockIdx.y;
    const int tid = threadIdx.x;
    const int lane = tid & 31, wid = tid >> 5;
    __shared__ float pv[224];
    __shared__ int   pj[224];
    __shared__ int   wbase[4];
    __shared__ float wsum[4];
    __shared__ int   s_cnt;
    __shared__ float s_sum;
    const float* Prow = g_P + (size_t)h * SEQ * SEQ + (size_t)s * SEQ;
    const unsigned* mb = g_M + (h * SEQ + s) * (SEQ / 32);

    float pr[8]; bool al[8];
    int c = 0; float lsum = 0.f;
    const int j0 = tid * 8;
#pragma unroll
    for (int u = 0; u < 8; u++) {
        const int j = j0 + u;
        bool a;
        if (s < HB) a = (j <= s);
        else        a = (j <= s) && ((j + RB >= s) || ((mb[j >> 5] >> (j & 31)) & 1u));
        float val = a ? Prow[j] : 0.f;
        al[u] = a; pr[u] = val;
        if (a) { c++; lsum += val; }
    }
    int inc = c;
#pragma unroll
    for (int o = 1; o < 32; o <<= 1) {
        int v = __shfl_up_sync(0xffffffffu, inc, o);
        if (lane >= o) inc += v;
    }
    float ws = lsum;
#pragma unroll
    for (int o = 16; o; o >>= 1) ws += __shfl_xor_sync(0xffffffffu, ws, o);
    if (lane == 31) wbase[wid] = inc;
    if (lane == 0)  wsum[wid] = ws;
    __syncthreads();
    if (tid == 0) {
        int tot = 0;
#pragma unroll
        for (int w = 0; w < 4; w++) { int b = wbase[w]; wbase[w] = tot; tot += b; }
        s_cnt = tot;
        s_sum = wsum[0] + wsum[1] + wsum[2] + wsum[3];
    }
    __syncthreads();
    int k = wbase[wid] + inc - c;
#pragma unroll
    for (int u = 0; u < 8; u++)
        if (al[u]) { pv[k] = pr[u]; pj[k] = j0 + u; k++; }
    __syncthreads();

    const int cnt = s_cnt;
    const float inv = 1.0f / s_sum;
    const float* Vh = g_V + h * HD + tid;
    float acc = 0.f;
    int m2 = 0;
    for (; m2 + 4 <= cnt; m2 += 4) {
        acc += pv[m2 + 0] * Vh[(size_t)pj[m2 + 0] * DMODEL];
        acc += pv[m2 + 1] * Vh[(size_t)pj[m2 + 1] * DMODEL];
        acc += pv[m2 + 2] * Vh[(size_t)pj[m2 + 2] * DMODEL];
        acc += pv[m2 + 3] * Vh[(size_t)pj[m2 + 3] * DMODEL];
    }
    for (; m2 < cnt; m2++) acc += pv[m2] * Vh[(size_t)pj[m2] * DMODEL];

    float v = acc * inv;
    __nv_bfloat16 hv = __float2bfloat16(v);
    size_t oi = (size_t)s * DMODEL + h * HD + tid;
    g_AOhi[oi] = hv;
    g_AOlo[oi] = __float2bfloat16(v - __bfloat162float(hv));
}

// ======================= launch =======================
extern "C" void kernel_launch(void* const* d_in, const int* in_sizes, int n_in,
                              void* d_out, int out_size)
{
    const float* X  = (const float*)d_in[0];
    const float* Wq = (const float*)d_in[2];
    const float* Wk = (const float*)d_in[3];
    const float* Wv = (const float*)d_in[4];
    const float* Wo = (const float*)d_in[5];
    float* out = (float*)d_out;

    cudaFuncSetAttribute(mm_qkv_kernel, cudaFuncAttributeMaxDynamicSharedMemorySize, MM_SMEM);
    cudaFuncSetAttribute(mm_qk_kernel,  cudaFuncAttributeMaxDynamicSharedMemorySize, MM_SMEM);
    cudaFuncSetAttribute(mm_o_kernel,   cudaFuncAttributeMaxDynamicSharedMemorySize, MM_SMEM);

    cvt_kernel<<<(SEQ * DMODEL / 4 + 255) / 256, 256>>>(X, SEQ * DMODEL / 4, 0);
    cvt_kernel<<<(DMODEL * DMODEL / 4 + 255) / 256, 256>>>(Wq, DMODEL * DMODEL / 4, 1);
    cvt_kernel<<<(DMODEL * DMODEL / 4 + 255) / 256, 256>>>(Wk, DMODEL * DMODEL / 4, 2);
    cvt_kernel<<<(DMODEL * DMODEL / 4 + 255) / 256, 256>>>(Wv, DMODEL * DMODEL / 4, 3);
    cvt_kernel<<<(DMODEL * DMODEL / 4 + 255) / 256, 256>>>(Wo, DMODEL * DMODEL / 4, 4);

    mm_qkv_kernel<<<dim3(DMODEL / 128, SEQ / 128, 3), 256, MM_SMEM>>>();
    rope_kernel<<<dim3((SEQ * NH * 64) / 256, 2), 256>>>();
    mm_qk_kernel<<<dim3(SEQ / 128, SEQ / 128, NH), 256, MM_SMEM>>>();
    softmax_kernel<<<dim3(SEQ, NH), 256>>>();
    scan_kernel<<<NH, 32>>>();
    pv_kernel<<<dim3(SEQ, NH), 128>>>();
    mm_o_kernel<<<dim3(DMODEL / 128, SEQ / 128), 256, MM_SMEM>>>(out);
}

// round 4
// speedup vs baseline: 1.6806x; 1.0809x over previous
#include <cuda_runtime.h>
#include <cuda_bf16.h>
#include <math.h>
#include <float.h>
#include <stdint.h>

#define SEQ 1024
#define DMODEL 4096
#define NH 32
#define HD 128
#define HB 102
#define RB 102

// ======================= static device scratch =======================
__device__ __align__(256) float g_Q[SEQ * DMODEL];
__device__ __align__(256) float g_K[SEQ * DMODEL];
__device__ __align__(256) float g_V[SEQ * DMODEL];
__device__ __align__(256) float g_P[(size_t)NH * SEQ * SEQ];
__device__ unsigned g_M[NH * SEQ * (SEQ / 32)];
__device__ __align__(256) __nv_bfloat16 g_Xhi[SEQ * DMODEL], g_Xlo[SEQ * DMODEL];
__device__ __align__(256) __nv_bfloat16 g_Whi[4][DMODEL * DMODEL];
__device__ __align__(256) __nv_bfloat16 g_Wlo[4][DMODEL * DMODEL];
__device__ __align__(256) __nv_bfloat16 g_Qhi[SEQ * DMODEL], g_Qlo[SEQ * DMODEL];
__device__ __align__(256) __nv_bfloat16 g_Khi[SEQ * DMODEL], g_Klo[SEQ * DMODEL];
__device__ __align__(256) __nv_bfloat16 g_AOhi[SEQ * DMODEL], g_AOlo[SEQ * DMODEL];

// ======================= helpers =======================
__device__ __forceinline__ uint32_t smem_u32(const void* p) {
    uint32_t a;
    asm("{ .reg .u64 t; cvta.to.shared.u64 t, %1; cvt.u32.u64 %0, t; }" : "=r"(a) : "l"(p));
    return a;
}
__device__ __forceinline__ void cp16(uint32_t dst, const void* src) {
    asm volatile("cp.async.cg.shared.global [%0], [%1], 16;" :: "r"(dst), "l"(src));
}
__device__ __forceinline__ void cp_commit() { asm volatile("cp.async.commit_group;" ::: "memory"); }
__device__ __forceinline__ void cp_wait1() { asm volatile("cp.async.wait_group 1;" ::: "memory"); }
__device__ __forceinline__ void cp_wait0() { asm volatile("cp.async.wait_group 0;" ::: "memory"); }

__device__ __forceinline__ void ldsm4(uint32_t* r, uint32_t addr) {
    asm volatile("ldmatrix.sync.aligned.m8n8.x4.shared.b16 {%0,%1,%2,%3}, [%4];"
        : "=r"(r[0]), "=r"(r[1]), "=r"(r[2]), "=r"(r[3]) : "r"(addr));
}
__device__ __forceinline__ void mma_bf16(float* c, const uint32_t* a, uint32_t b0, uint32_t b1) {
    asm volatile("mma.sync.aligned.m16n8k16.row.col.f32.bf16.bf16.f32 "
        "{%0,%1,%2,%3}, {%4,%5,%6,%7}, {%8,%9}, {%0,%1,%2,%3};"
        : "+f"(c[0]), "+f"(c[1]), "+f"(c[2]), "+f"(c[3])
        : "r"(a[0]), "r"(a[1]), "r"(a[2]), "r"(a[3]), "r"(b0), "r"(b1));
}

// ======================= split-bf16 HMMA GEMM core =======================
// C[256 x 128] = (Ahi+Alo)[256 x K] * (Bhi+Blo)[128 x K]^T   (lo*lo dropped)
// BK = 64, double-buffered cp.async, XOR-swizzled smem (128B rows).
// 512 threads = 16 warps: warp grid 8(M) x 2(N), warp tile 32 x 64.
#define A_SLAB 32768                  /* 256 x 128B */
#define B_SLAB 16384                  /* 128 x 128B */
#define STAGE (2 * A_SLAB + 2 * B_SLAB)   /* Ahi|Alo|Bhi|Blo = 98304 */
#define MM_SMEM (2 * STAGE)               /* 196608 */

__device__ __forceinline__ void ld_stage(
    uint32_t st, const __nv_bfloat16* Ahi, const __nv_bfloat16* Alo,
    const __nv_bfloat16* Bhi, const __nv_bfloat16* Blo,
    int lda, int ldb, int k0, int tid)
{
#pragma unroll
    for (int it = 0; it < 4; it++) {          // A: 256 rows x 8 granules
        int idx = it * 512 + tid;
        int row = idx >> 3, g = idx & 7;
        uint32_t off = row * 128 + ((g ^ (row & 7)) << 4);
        size_t s = (size_t)row * lda + k0 + g * 8;
        cp16(st + off, Ahi + s);
        cp16(st + A_SLAB + off, Alo + s);
    }
#pragma unroll
    for (int it = 0; it < 2; it++) {          // B: 128 rows x 8 granules
        int idx = it * 512 + tid;
        int row = idx >> 3, g = idx & 7;
        uint32_t off = row * 128 + ((g ^ (row & 7)) << 4);
        size_t s = (size_t)row * ldb + k0 + g * 8;
        cp16(st + 2 * A_SLAB + off, Bhi + s);
        cp16(st + 2 * A_SLAB + B_SLAB + off, Blo + s);
    }
}

__device__ __forceinline__ void mm_hmma(
    const __nv_bfloat16* __restrict__ Ahi, const __nv_bfloat16* __restrict__ Alo, int lda,
    const __nv_bfloat16* __restrict__ Bhi, const __nv_bfloat16* __restrict__ Blo, int ldb,
    float* __restrict__ C, int ldc, int nk, float scale)
{
    extern __shared__ char smem[];
    const uint32_t sb = smem_u32(smem);
    const int tid = threadIdx.x, lane = tid & 31, wid = tid >> 5;
    const int wm = wid & 7, wn = wid >> 3;

    float c[2][8][4];
#pragma unroll
    for (int i = 0; i < 2; i++)
#pragma unroll
        for (int j = 0; j < 8; j++)
#pragma unroll
            for (int q = 0; q < 4; q++) c[i][j][q] = 0.f;

    ld_stage(sb, Ahi, Alo, Bhi, Blo, lda, ldb, 0, tid); cp_commit();
    ld_stage(sb + STAGE, Ahi, Alo, Bhi, Blo, lda, ldb, 64, tid); cp_commit();

    const int axor = lane & 7;                 // row&7 for both A and B frag rows
    for (int ck = 0; ck < nk; ck++) {
        if (ck == nk - 1) cp_wait0(); else cp_wait1();
        __syncthreads();
        const uint32_t st = sb + (ck & 1) * STAGE;
#pragma unroll
        for (int k16 = 0; k16 < 4; k16++) {
            uint32_t ah[2][4], al[2][4];
#pragma unroll
            for (int i = 0; i < 2; i++) {
                int arow = wm * 32 + i * 16 + (lane & 15);
                uint32_t ad = st + (uint32_t)(arow * 128)
                            + (uint32_t)(((2 * k16 + (lane >> 4)) ^ axor) << 4);
                ldsm4(ah[i], ad);
                ldsm4(al[i], ad + A_SLAB);
            }
#pragma unroll
            for (int j4 = 0; j4 < 4; j4++) {
                int brow = wn * 64 + j4 * 16 + ((lane >> 4) << 3) + (lane & 7);
                uint32_t bd = st + 2 * A_SLAB + (uint32_t)(brow * 128)
                            + (uint32_t)(((2 * k16 + ((lane >> 3) & 1)) ^ axor) << 4);
                uint32_t bh[4], bl[4];
                ldsm4(bh, bd);
                ldsm4(bl, bd + B_SLAB);
#pragma unroll
                for (int i = 0; i < 2; i++) {
                    mma_bf16(c[i][2 * j4],     ah[i], bh[0], bh[1]);
                    mma_bf16(c[i][2 * j4],     ah[i], bl[0], bl[1]);
                    mma_bf16(c[i][2 * j4],     al[i], bh[0], bh[1]);
                    mma_bf16(c[i][2 * j4 + 1], ah[i], bh[2], bh[3]);
                    mma_bf16(c[i][2 * j4 + 1], ah[i], bl[2], bl[3]);
                    mma_bf16(c[i][2 * j4 + 1], al[i], bh[2], bh[3]);
                }
            }
        }
        __syncthreads();
        if (ck + 2 < nk) {
            ld_stage(st, Ahi, Alo, Bhi, Blo, lda, ldb, (ck + 2) * 64, tid);
            cp_commit();
        }
    }

    const int r0 = wm * 32 + (lane >> 2);
    const int c0 = wn * 64 + (lane & 3) * 2;
#pragma unroll
    for (int i = 0; i < 2; i++)
#pragma unroll
        for (int j = 0; j < 8; j++) {
            float2 v0 = { c[i][j][0] * scale, c[i][j][1] * scale };
            float2 v1 = { c[i][j][2] * scale, c[i][j][3] * scale };
            *(float2*)&C[(size_t)(r0 + i * 16) * ldc + c0 + j * 8] = v0;
            *(float2*)&C[(size_t)(r0 + i * 16 + 8) * ldc + c0 + j * 8] = v1;
        }
}

// ======================= fused conversion fp32 -> bf16 hi/lo =======================
#define X4 (SEQ * DMODEL / 4)
#define W4 (DMODEL * DMODEL / 4)
__global__ __launch_bounds__(256) void cvt_all_kernel(
    const float* __restrict__ X, const float* __restrict__ Wq,
    const float* __restrict__ Wk, const float* __restrict__ Wv,
    const float* __restrict__ Wo)
{
    long long i = (long long)blockIdx.x * 256 + threadIdx.x;
    const float* src;
    __nv_bfloat16 *hi, *lo;
    long long r;
    if (i < X4)                    { src = X;  hi = g_Xhi;    lo = g_Xlo;    r = i; }
    else if ((r = i - X4) < W4)    { src = Wq; hi = g_Whi[0]; lo = g_Wlo[0]; }
    else if ((r -= W4) < W4)       { src = Wk; hi = g_Whi[1]; lo = g_Wlo[1]; }
    else if ((r -= W4) < W4)       { src = Wv; hi = g_Whi[2]; lo = g_Wlo[2]; }
    else if ((r -= W4) < W4)       { src = Wo; hi = g_Whi[3]; lo = g_Wlo[3]; }
    else return;
    float4 v = ((const float4*)src)[r];
    __nv_bfloat16 h0 = __float2bfloat16(v.x), h1 = __float2bfloat16(v.y);
    __nv_bfloat16 h2 = __float2bfloat16(v.z), h3 = __float2bfloat16(v.w);
    __nv_bfloat162 H01; H01.x = h0; H01.y = h1;
    __nv_bfloat162 H23; H23.x = h2; H23.y = h3;
    __nv_bfloat162 L01, L23;
    L01.x = __float2bfloat16(v.x - __bfloat162float(h0));
    L01.y = __float2bfloat16(v.y - __bfloat162float(h1));
    L23.x = __float2bfloat16(v.z - __bfloat162float(h2));
    L23.y = __float2bfloat16(v.w - __bfloat162float(h3));
    *(__nv_bfloat162*)(hi + 4 * (size_t)r)     = H01;
    *(__nv_bfloat162*)(hi + 4 * (size_t)r + 2) = H23;
    *(__nv_bfloat162*)(lo + 4 * (size_t)r)     = L01;
    *(__nv_bfloat162*)(lo + 4 * (size_t)r + 2) = L23;
}

// ======================= GEMM wrappers =======================
__global__ __launch_bounds__(512, 1) void mm_qkv_kernel()
{
    const int z = blockIdx.z;
    const int m0 = blockIdx.y * 256, n0 = blockIdx.x * 128;
    float* O = (z == 0) ? g_Q : (z == 1) ? g_K : g_V;
    mm_hmma(g_Xhi + (size_t)m0 * DMODEL, g_Xlo + (size_t)m0 * DMODEL, DMODEL,
            g_Whi[z] + (size_t)n0 * DMODEL, g_Wlo[z] + (size_t)n0 * DMODEL, DMODEL,
            O + (size_t)m0 * DMODEL + n0, DMODEL, DMODEL / 64, 1.0f);
}

__global__ __launch_bounds__(512, 1) void mm_o_kernel(float* __restrict__ out)
{
    const int m0 = blockIdx.y * 256, n0 = blockIdx.x * 128;
    mm_hmma(g_AOhi + (size_t)m0 * DMODEL, g_AOlo + (size_t)m0 * DMODEL, DMODEL,
            g_Whi[3] + (size_t)n0 * DMODEL, g_Wlo[3] + (size_t)n0 * DMODEL, DMODEL,
            out + (size_t)m0 * DMODEL + n0, DMODEL, DMODEL / 64, 1.0f);
}

__global__ __launch_bounds__(512, 1) void mm_qk_kernel()
{
    const int h = blockIdx.z;
    const int m0 = blockIdx.y * 256, n0 = blockIdx.x * 128;
    if (n0 > m0 + 255) return;   // tile entirely above diagonal: never read
    mm_hmma(g_Qhi + (size_t)m0 * DMODEL + h * HD, g_Qlo + (size_t)m0 * DMODEL + h * HD, DMODEL,
            g_Khi + (size_t)n0 * DMODEL + h * HD, g_Klo + (size_t)n0 * DMODEL + h * HD, DMODEL,
            g_P + (size_t)h * SEQ * SEQ + (size_t)m0 * SEQ + n0, SEQ,
            HD / 64, 0.08838834764831845f);
}

// ======================= RoPE: fp32 Q/K -> roped bf16 hi/lo =======================
__global__ void rope_kernel()
{
    int idx = blockIdx.x * blockDim.x + threadIdx.x;   // [0, 1024*32*64)
    const float* src = blockIdx.y ? g_K : g_Q;
    __nv_bfloat16* hi = blockIdx.y ? g_Khi : g_Qhi;
    __nv_bfloat16* lo = blockIdx.y ? g_Klo : g_Qlo;
    int p = idx & 63;
    int h = (idx >> 6) & 31;
    int s = idx >> 11;
    float inv = 1.0f / powf(10000.0f, (float)(2 * p) * (1.0f / 128.0f));
    float ang = (float)s * inv;
    float sn, c;
    sincosf(ang, &sn, &c);
    size_t b = (size_t)s * DMODEL + h * HD + p;
    float q0 = src[b], q1 = src[b + 64];
    float r0 = q0 * c - q1 * sn;
    float r1 = q1 * c + q0 * sn;
    __nv_bfloat16 h0 = __float2bfloat16(r0);
    __nv_bfloat16 h1 = __float2bfloat16(r1);
    hi[b] = h0;      lo[b]      = __float2bfloat16(r0 - __bfloat162float(h0));
    hi[b + 64] = h1; lo[b + 64] = __float2bfloat16(r1 - __bfloat162float(h1));
}

// ======================= softmax (probs P0, zero above diagonal) =======================
__global__ __launch_bounds__(256) void softmax_kernel()
{
    const int i = blockIdx.x, h = blockIdx.y;
    float* row = g_P + (size_t)h * SEQ * SEQ + (size_t)i * SEQ;
    const int n = i + 1;
    const int tid = threadIdx.x;
    const int lane = tid & 31, wid = tid >> 5;
    __shared__ float red[16];

    float m = -FLT_MAX;
    for (int j = tid; j < n; j += 256) m = fmaxf(m, row[j]);
#pragma unroll
    for (int o = 16; o; o >>= 1) m = fmaxf(m, __shfl_xor_sync(0xffffffffu, m, o));
    if (lane == 0) red[wid] = m;
    __syncthreads();
    m = red[0];
#pragma unroll
    for (int w = 1; w < 8; w++) m = fmaxf(m, red[w]);

    float s = 0.f;
    for (int j = tid; j < n; j += 256) s += expf(row[j] - m);
#pragma unroll
    for (int o = 16; o; o >>= 1) s += __shfl_xor_sync(0xffffffffu, s, o);
    if (lane == 0) red[8 + wid] = s;
    __syncthreads();
    float tot = 0.f;
#pragma unroll
    for (int w = 0; w < 8; w++) tot += red[8 + w];
    const float invs = 1.0f / tot;

    for (int j = tid; j < SEQ; j += 256)
        row[j] = (j < n) ? expf(row[j] - m) * invs : 0.f;
}

// ======================= H2O sequential scan, one warp per head =======================
__global__ void scan_kernel()
{
    const int h = blockIdx.x;
    const int lane = threadIdx.x;
    __shared__ float acc[SEQ];
    __shared__ int   lst[128];
    __shared__ float skey[128];
    __shared__ unsigned mw[32];
    const float* P = g_P + (size_t)h * SEQ * SEQ;
    unsigned* MB = g_M + h * SEQ * (SEQ / 32);

    for (int j = lane; j < SEQ; j += 32) acc[j] = 0.f;
    __syncwarp();
    for (int j = lane; j < HB; j += 32) {
        float s = 0.f;
        for (int i = 0; i < HB; i++) s += P[(size_t)i * SEQ + j];
        acc[j] = s;
    }
    for (int p = lane; p < HB; p += 32) lst[p] = p;
    int cnt = HB;
    __syncwarp();

    for (int t = HB; t < SEQ; t++) {
        const float* Prow = P + (size_t)t * SEQ;
        for (int p = lane; p < cnt; p += 32) {
            const float* a = Prow + lst[p];
            asm volatile("prefetch.global.L2 [%0];" :: "l"(a));
        }
        if (lane == 0) {
            const float* a = Prow + t;
            asm volatile("prefetch.global.L2 [%0];" :: "l"(a));
        }

        for (int p = lane; p < cnt; p += 32) skey[p] = acc[lst[p]];
        __syncwarp();

        const int r = cnt - (HB - 1);
        for (int rep = 0; rep < r; rep++) {
            float bv = FLT_MAX; int bidx = -1; int bpos = 0;
            for (int p = lane; p < cnt; p += 32) {
                float v = skey[p]; int ix = lst[p];
                if (v < bv || (v == bv && ix > bidx)) { bv = v; bidx = ix; bpos = p; }
            }
#pragma unroll
            for (int o = 16; o; o >>= 1) {
                float ov = __shfl_down_sync(0xffffffffu, bv, o);
                int   oi = __shfl_down_sync(0xffffffffu, bidx, o);
                int   op = __shfl_down_sync(0xffffffffu, bpos, o);
                if (ov < bv || (ov == bv && oi > bidx)) { bv = ov; bidx = oi; bpos = op; }
            }
            bidx = __shfl_sync(0xffffffffu, bidx, 0);
            bpos = __shfl_sync(0xffffffffu, bpos, 0);
            if (bidx >= 4) {
                if (lane == 0) {
                    acc[bidx] = 0.f;
                    lst[bpos]  = lst[cnt - 1];
                    skey[bpos] = skey[cnt - 1];
                }
                cnt--;
            } else {
                if (lane == 0) skey[bpos] = FLT_MAX;
            }
            __syncwarp();
        }
        if (lane == 0) lst[cnt] = t;
        cnt++;
        mw[lane] = 0u;
        __syncwarp();
        for (int p = lane; p < cnt; p += 32) {
            int ix = lst[p];
            acc[ix] += Prow[ix];
            atomicOr(&mw[ix >> 5], 1u << (ix & 31));
        }
        __syncwarp();
        MB[t * 32 + lane] = mw[lane];
        __syncwarp();
    }
}

// ======================= masked renorm softmax + P@V (writes AO hi/lo) =======================
__global__ __launch_bounds__(128) void pv_kernel()
{
    const int s = blockIdx.x, h = blockIdx.y;
    const int tid = threadIdx.x;
    const int lane = tid & 31, wid = tid >> 5;
    __shared__ float pv[224];
    __shared__ int   pj[224];
    __shared__ int   wbase[4];
    __shared__ float wsum[4];
    __shared__ int   s_cnt;
    __shared__ float s_sum;
    const float* Prow = g_P + (size_t)h * SEQ * SEQ + (size_t)s * SEQ;
    const unsigned* mb = g_M + (h * SEQ + s) * (SEQ / 32);

    float pr[8]; bool al[8];
    int c = 0; float lsum = 0.f;
    const int j0 = tid * 8;
#pragma unroll
    for (int u = 0; u < 8; u++) {
        const int j = j0 + u;
        bool a;
        if (s < HB) a = (j <= s);
        else        a = (j <= s) && ((j + RB >= s) || ((mb[j >> 5] >> (j & 31)) & 1u));
        float val = a ? Prow[j] : 0.f;
        al[u] = a; pr[u] = val;
        if (a) { c++; lsum += val; }
    }
    int inc = c;
#pragma unroll
    for (int o = 1; o < 32; o <<= 1) {
        int v = __shfl_up_sync(0xffffffffu, inc, o);
        if (lane >= o) inc += v;
    }
    float ws = lsum;
#pragma unroll
    for (int o = 16; o; o >>= 1) ws += __shfl_xor_sync(0xffffffffu, ws, o);
    if (lane == 31) wbase[wid] = inc;
    if (lane == 0)  wsum[wid] = ws;
    __syncthreads();
    if (tid == 0) {
        int tot = 0;
#pragma unroll
        for (int w = 0; w < 4; w++) { int b = wbase[w]; wbase[w] = tot; tot += b; }
        s_cnt = tot;
        s_sum = wsum[0] + wsum[1] + wsum[2] + wsum[3];
    }
    __syncthreads();
    int k = wbase[wid] + inc - c;
#pragma unroll
    for (int u = 0; u < 8; u++)
        if (al[u]) { pv[k] = pr[u]; pj[k] = j0 + u; k++; }
    __syncthreads();

    const int cnt = s_cnt;
    const float inv = 1.0f / s_sum;
    const float* Vh = g_V + h * HD + tid;
    float acc = 0.f;
    int m2 = 0;
    for (; m2 + 4 <= cnt; m2 += 4) {
        acc += pv[m2 + 0] * Vh[(size_t)pj[m2 + 0] * DMODEL];
        acc += pv[m2 + 1] * Vh[(size_t)pj[m2 + 1] * DMODEL];
        acc += pv[m2 + 2] * Vh[(size_t)pj[m2 + 2] * DMODEL];
        acc += pv[m2 + 3] * Vh[(size_t)pj[m2 + 3] * DMODEL];
    }
    for (; m2 < cnt; m2++) acc += pv[m2] * Vh[(size_t)pj[m2] * DMODEL];

    float v = acc * inv;
    __nv_bfloat16 hv = __float2bfloat16(v);
    size_t oi = (size_t)s * DMODEL + h * HD + tid;
    g_AOhi[oi] = hv;
    g_AOlo[oi] = __float2bfloat16(v - __bfloat162float(hv));
}

// ======================= launch =======================
extern "C" void kernel_launch(void* const* d_in, const int* in_sizes, int n_in,
                              void* d_out, int out_size)
{
    const float* X  = (const float*)d_in[0];
    const float* Wq = (const float*)d_in[2];
    const float* Wk = (const float*)d_in[3];
    const float* Wv = (const float*)d_in[4];
    const float* Wo = (const float*)d_in[5];
    float* out = (float*)d_out;

    cudaFuncSetAttribute(mm_qkv_kernel, cudaFuncAttributeMaxDynamicSharedMemorySize, MM_SMEM);
    cudaFuncSetAttribute(mm_qk_kernel,  cudaFuncAttributeMaxDynamicSharedMemorySize, MM_SMEM);
    cudaFuncSetAttribute(mm_o_kernel,   cudaFuncAttributeMaxDynamicSharedMemorySize, MM_SMEM);

    cvt_all_kernel<<<(X4 + 4 * W4 + 255) / 256, 256>>>(X, Wq, Wk, Wv, Wo);
    mm_qkv_kernel<<<dim3(DMODEL / 128, SEQ / 256, 3), 512, MM_SMEM>>>();
    rope_kernel<<<dim3((SEQ * NH * 64) / 256, 2), 256>>>();
    mm_qk_kernel<<<dim3(SEQ / 128, SEQ / 256, NH), 512, MM_SMEM>>>();
    softmax_kernel<<<dim3(SEQ, NH), 256>>>();
    scan_kernel<<<NH, 32>>>();
    pv_kernel<<<dim3(SEQ, NH), 128>>>();
    mm_o_kernel<<<dim3(DMODEL / 128, SEQ / 256), 512, MM_SMEM>>>(out);
}

// round 5
// speedup vs baseline: 1.6950x; 1.0086x over previous
#include <cuda_runtime.h>
#include <cuda_bf16.h>
#include <math.h>
#include <float.h>
#include <stdint.h>

#define SEQ 1024
#define DMODEL 4096
#define NH 32
#define HD 128
#define HB 102
#define RB 102

// ======================= static device scratch =======================
__device__ __align__(256) float g_Q[SEQ * DMODEL];
__device__ __align__(256) float g_K[SEQ * DMODEL];
__device__ __align__(256) float g_V[SEQ * DMODEL];
__device__ __align__(256) float g_P[(size_t)NH * SEQ * SEQ];
__device__ unsigned g_M[NH * SEQ * (SEQ / 32)];
__device__ __align__(256) __nv_bfloat16 g_Xhi[SEQ * DMODEL], g_Xlo[SEQ * DMODEL];
__device__ __align__(256) __nv_bfloat16 g_Whi[4][DMODEL * DMODEL];
__device__ __align__(256) __nv_bfloat16 g_Wlo[4][DMODEL * DMODEL];
__device__ __align__(256) __nv_bfloat16 g_Qhi[SEQ * DMODEL], g_Qlo[SEQ * DMODEL];
__device__ __align__(256) __nv_bfloat16 g_Khi[SEQ * DMODEL], g_Klo[SEQ * DMODEL];
__device__ __align__(256) __nv_bfloat16 g_AOhi[SEQ * DMODEL], g_AOlo[SEQ * DMODEL];

// ======================= helpers =======================
__device__ __forceinline__ uint32_t smem_u32(const void* p) {
    uint32_t a;
    asm("{ .reg .u64 t; cvta.to.shared.u64 t, %1; cvt.u32.u64 %0, t; }" : "=r"(a) : "l"(p));
    return a;
}
__device__ __forceinline__ void cp16(uint32_t dst, const void* src) {
    asm volatile("cp.async.cg.shared.global [%0], [%1], 16;" :: "r"(dst), "l"(src));
}
__device__ __forceinline__ void cp_commit() { asm volatile("cp.async.commit_group;" ::: "memory"); }
__device__ __forceinline__ void cp_wait1() { asm volatile("cp.async.wait_group 1;" ::: "memory"); }
__device__ __forceinline__ void cp_wait0() { asm volatile("cp.async.wait_group 0;" ::: "memory"); }

__device__ __forceinline__ void ldsm4(uint32_t* r, uint32_t addr) {
    asm volatile("ldmatrix.sync.aligned.m8n8.x4.shared.b16 {%0,%1,%2,%3}, [%4];"
        : "=r"(r[0]), "=r"(r[1]), "=r"(r[2]), "=r"(r[3]) : "r"(addr));
}
__device__ __forceinline__ void mma_bf16(float* c, const uint32_t* a, uint32_t b0, uint32_t b1) {
    asm volatile("mma.sync.aligned.m16n8k16.row.col.f32.bf16.bf16.f32 "
        "{%0,%1,%2,%3}, {%4,%5,%6,%7}, {%8,%9}, {%0,%1,%2,%3};"
        : "+f"(c[0]), "+f"(c[1]), "+f"(c[2]), "+f"(c[3])
        : "r"(a[0]), "r"(a[1]), "r"(a[2]), "r"(a[3]), "r"(b0), "r"(b1));
}

// ======================= split-bf16 HMMA GEMM core =======================
// C[128 x 64] = (Ahi+Alo)[128 x K] * (Bhi+Blo)[64 x K]^T   (lo*lo dropped)
// BK = 64, double-buffered cp.async, XOR-swizzled smem (128B rows).
// 256 threads = 8 warps: warp grid 4(M) x 2(N), warp tile 32 x 32.
// 96KB total smem -> 2 CTAs/SM (32 warps) for latency hiding.
#define A_SLAB 16384                  /* 128 x 128B */
#define B_SLAB 8192                   /*  64 x 128B */
#define STAGE (2 * A_SLAB + 2 * B_SLAB)   /* Ahi|Alo|Bhi|Blo = 49152 */
#define MM_SMEM (2 * STAGE)               /* 98304 */

__device__ __forceinline__ void ld_stage(
    uint32_t st, const __nv_bfloat16* Ahi, const __nv_bfloat16* Alo,
    const __nv_bfloat16* Bhi, const __nv_bfloat16* Blo,
    int lda, int ldb, int k0, int tid)
{
#pragma unroll
    for (int it = 0; it < 4; it++) {          // A: 128 rows x 8 granules = 1024
        int idx = it * 256 + tid;
        int row = idx >> 3, g = idx & 7;
        uint32_t off = row * 128 + ((g ^ (row & 7)) << 4);
        size_t s = (size_t)row * lda + k0 + g * 8;
        cp16(st + off, Ahi + s);
        cp16(st + A_SLAB + off, Alo + s);
    }
#pragma unroll
    for (int it = 0; it < 2; it++) {          // B: 64 rows x 8 granules = 512
        int idx = it * 256 + tid;
        int row = idx >> 3, g = idx & 7;
        uint32_t off = row * 128 + ((g ^ (row & 7)) << 4);
        size_t s = (size_t)row * ldb + k0 + g * 8;
        cp16(st + 2 * A_SLAB + off, Bhi + s);
        cp16(st + 2 * A_SLAB + B_SLAB + off, Blo + s);
    }
}

__device__ __forceinline__ void mm_hmma(
    const __nv_bfloat16* __restrict__ Ahi, const __nv_bfloat16* __restrict__ Alo, int lda,
    const __nv_bfloat16* __restrict__ Bhi, const __nv_bfloat16* __restrict__ Blo, int ldb,
    float* __restrict__ C, int ldc, int nk, float scale)
{
    extern __shared__ char smem[];
    const uint32_t sb = smem_u32(smem);
    const int tid = threadIdx.x, lane = tid & 31, wid = tid >> 5;
    const int wm = wid & 3, wn = wid >> 2;

    float c[2][4][4];
#pragma unroll
    for (int i = 0; i < 2; i++)
#pragma unroll
        for (int j = 0; j < 4; j++)
#pragma unroll
            for (int q = 0; q < 4; q++) c[i][j][q] = 0.f;

    ld_stage(sb, Ahi, Alo, Bhi, Blo, lda, ldb, 0, tid); cp_commit();
    ld_stage(sb + STAGE, Ahi, Alo, Bhi, Blo, lda, ldb, 64, tid); cp_commit();

    const int axor = lane & 7;
    for (int ck = 0; ck < nk; ck++) {
        if (ck == nk - 1) cp_wait0(); else cp_wait1();
        __syncthreads();
        const uint32_t st = sb + (ck & 1) * STAGE;
#pragma unroll
        for (int k16 = 0; k16 < 4; k16++) {
            uint32_t ah[2][4], al[2][4];
#pragma unroll
            for (int i = 0; i < 2; i++) {
                int arow = wm * 32 + i * 16 + (lane & 15);
                uint32_t ad = st + (uint32_t)(arow * 128)
                            + (uint32_t)(((2 * k16 + (lane >> 4)) ^ axor) << 4);
                ldsm4(ah[i], ad);
                ldsm4(al[i], ad + A_SLAB);
            }
#pragma unroll
            for (int j4 = 0; j4 < 2; j4++) {
                int brow = wn * 32 + j4 * 16 + ((lane >> 4) << 3) + (lane & 7);
                uint32_t bd = st + 2 * A_SLAB + (uint32_t)(brow * 128)
                            + (uint32_t)(((2 * k16 + ((lane >> 3) & 1)) ^ axor) << 4);
                uint32_t bh[4], bl[4];
                ldsm4(bh, bd);
                ldsm4(bl, bd + B_SLAB);
#pragma unroll
                for (int i = 0; i < 2; i++) {
                    mma_bf16(c[i][2 * j4],     ah[i], bh[0], bh[1]);
                    mma_bf16(c[i][2 * j4],     ah[i], bl[0], bl[1]);
                    mma_bf16(c[i][2 * j4],     al[i], bh[0], bh[1]);
                    mma_bf16(c[i][2 * j4 + 1], ah[i], bh[2], bh[3]);
                    mma_bf16(c[i][2 * j4 + 1], ah[i], bl[2], bl[3]);
                    mma_bf16(c[i][2 * j4 + 1], al[i], bh[2], bh[3]);
                }
            }
        }
        __syncthreads();
        if (ck + 2 < nk) {
            ld_stage(st, Ahi, Alo, Bhi, Blo, lda, ldb, (ck + 2) * 64, tid);
            cp_commit();
        }
    }

    const int r0 = wm * 32 + (lane >> 2);
    const int c0 = wn * 32 + (lane & 3) * 2;
#pragma unroll
    for (int i = 0; i < 2; i++)
#pragma unroll
        for (int j = 0; j < 4; j++) {
            float2 v0 = { c[i][j][0] * scale, c[i][j][1] * scale };
            float2 v1 = { c[i][j][2] * scale, c[i][j][3] * scale };
            *(float2*)&C[(size_t)(r0 + i * 16) * ldc + c0 + j * 8] = v0;
            *(float2*)&C[(size_t)(r0 + i * 16 + 8) * ldc + c0 + j * 8] = v1;
        }
}

// ======================= fused conversion fp32 -> bf16 hi/lo =======================
#define X4 (SEQ * DMODEL / 4)
#define W4 (DMODEL * DMODEL / 4)
__global__ __launch_bounds__(256) void cvt_all_kernel(
    const float* __restrict__ X, const float* __restrict__ Wq,
    const float* __restrict__ Wk, const float* __restrict__ Wv,
    const float* __restrict__ Wo)
{
    long long i = (long long)blockIdx.x * 256 + threadIdx.x;
    const float* src;
    __nv_bfloat16 *hi, *lo;
    long long r;
    if (i < X4)                    { src = X;  hi = g_Xhi;    lo = g_Xlo;    r = i; }
    else if ((r = i - X4) < W4)    { src = Wq; hi = g_Whi[0]; lo = g_Wlo[0]; }
    else if ((r -= W4) < W4)       { src = Wk; hi = g_Whi[1]; lo = g_Wlo[1]; }
    else if ((r -= W4) < W4)       { src = Wv; hi = g_Whi[2]; lo = g_Wlo[2]; }
    else if ((r -= W4) < W4)       { src = Wo; hi = g_Whi[3]; lo = g_Wlo[3]; }
    else return;
    float4 v = ((const float4*)src)[r];
    __nv_bfloat16 h0 = __float2bfloat16(v.x), h1 = __float2bfloat16(v.y);
    __nv_bfloat16 h2 = __float2bfloat16(v.z), h3 = __float2bfloat16(v.w);
    __nv_bfloat162 H01; H01.x = h0; H01.y = h1;
    __nv_bfloat162 H23; H23.x = h2; H23.y = h3;
    __nv_bfloat162 L01, L23;
    L01.x = __float2bfloat16(v.x - __bfloat162float(h0));
    L01.y = __float2bfloat16(v.y - __bfloat162float(h1));
    L23.x = __float2bfloat16(v.z - __bfloat162float(h2));
    L23.y = __float2bfloat16(v.w - __bfloat162float(h3));
    *(__nv_bfloat162*)(hi + 4 * (size_t)r)     = H01;
    *(__nv_bfloat162*)(hi + 4 * (size_t)r + 2) = H23;
    *(__nv_bfloat162*)(lo + 4 * (size_t)r)     = L01;
    *(__nv_bfloat162*)(lo + 4 * (size_t)r + 2) = L23;
}

// ======================= GEMM wrappers =======================
__global__ __launch_bounds__(256, 2) void mm_qkv_kernel()
{
    const int z = blockIdx.z;
    const int m0 = blockIdx.y * 128, n0 = blockIdx.x * 64;
    float* O = (z == 0) ? g_Q : (z == 1) ? g_K : g_V;
    mm_hmma(g_Xhi + (size_t)m0 * DMODEL, g_Xlo + (size_t)m0 * DMODEL, DMODEL,
            g_Whi[z] + (size_t)n0 * DMODEL, g_Wlo[z] + (size_t)n0 * DMODEL, DMODEL,
            O + (size_t)m0 * DMODEL + n0, DMODEL, DMODEL / 64, 1.0f);
}

__global__ __launch_bounds__(256, 2) void mm_o_kernel(float* __restrict__ out)
{
    const int m0 = blockIdx.y * 128, n0 = blockIdx.x * 64;
    mm_hmma(g_AOhi + (size_t)m0 * DMODEL, g_AOlo + (size_t)m0 * DMODEL, DMODEL,
            g_Whi[3] + (size_t)n0 * DMODEL, g_Wlo[3] + (size_t)n0 * DMODEL, DMODEL,
            out + (size_t)m0 * DMODEL + n0, DMODEL, DMODEL / 64, 1.0f);
}

__global__ __launch_bounds__(256, 2) void mm_qk_kernel()
{
    const int h = blockIdx.z;
    const int m0 = blockIdx.y * 128, n0 = blockIdx.x * 64;
    if (n0 > m0 + 127) return;   // tile entirely above diagonal: never read
    mm_hmma(g_Qhi + (size_t)m0 * DMODEL + h * HD, g_Qlo + (size_t)m0 * DMODEL + h * HD, DMODEL,
            g_Khi + (size_t)n0 * DMODEL + h * HD, g_Klo + (size_t)n0 * DMODEL + h * HD, DMODEL,
            g_P + (size_t)h * SEQ * SEQ + (size_t)m0 * SEQ + n0, SEQ,
            HD / 64, 0.08838834764831845f);
}

// ======================= RoPE: fp32 Q/K -> roped bf16 hi/lo =======================
__global__ void rope_kernel()
{
    int idx = blockIdx.x * blockDim.x + threadIdx.x;   // [0, 1024*32*64)
    const float* src = blockIdx.y ? g_K : g_Q;
    __nv_bfloat16* hi = blockIdx.y ? g_Khi : g_Qhi;
    __nv_bfloat16* lo = blockIdx.y ? g_Klo : g_Qlo;
    int p = idx & 63;
    int h = (idx >> 6) & 31;
    int s = idx >> 11;
    float inv = 1.0f / powf(10000.0f, (float)(2 * p) * (1.0f / 128.0f));
    float ang = (float)s * inv;
    float sn, c;
    sincosf(ang, &sn, &c);
    size_t b = (size_t)s * DMODEL + h * HD + p;
    float q0 = src[b], q1 = src[b + 64];
    float r0 = q0 * c - q1 * sn;
    float r1 = q1 * c + q0 * sn;
    __nv_bfloat16 h0 = __float2bfloat16(r0);
    __nv_bfloat16 h1 = __float2bfloat16(r1);
    hi[b] = h0;      lo[b]      = __float2bfloat16(r0 - __bfloat162float(h0));
    hi[b + 64] = h1; lo[b + 64] = __float2bfloat16(r1 - __bfloat162float(h1));
}

// ======================= softmax (probs P0, zero above diagonal) =======================
__global__ __launch_bounds__(256) void softmax_kernel()
{
    const int i = blockIdx.x, h = blockIdx.y;
    float* row = g_P + (size_t)h * SEQ * SEQ + (size_t)i * SEQ;
    const int n = i + 1;
    const int tid = threadIdx.x;
    const int lane = tid & 31, wid = tid >> 5;
    __shared__ float red[16];

    float m = -FLT_MAX;
    for (int j = tid; j < n; j += 256) m = fmaxf(m, row[j]);
#pragma unroll
    for (int o = 16; o; o >>= 1) m = fmaxf(m, __shfl_xor_sync(0xffffffffu, m, o));
    if (lane == 0) red[wid] = m;
    __syncthreads();
    m = red[0];
#pragma unroll
    for (int w = 1; w < 8; w++) m = fmaxf(m, red[w]);

    float s = 0.f;
    for (int j = tid; j < n; j += 256) s += expf(row[j] - m);
#pragma unroll
    for (int o = 16; o; o >>= 1) s += __shfl_xor_sync(0xffffffffu, s, o);
    if (lane == 0) red[8 + wid] = s;
    __syncthreads();
    float tot = 0.f;
#pragma unroll
    for (int w = 0; w < 8; w++) tot += red[8 + w];
    const float invs = 1.0f / tot;

    for (int j = tid; j < SEQ; j += 256)
        row[j] = (j < n) ? expf(row[j] - m) * invs : 0.f;
}

// ======================= H2O sequential scan, one warp per head =======================
__global__ void scan_kernel()
{
    const int h = blockIdx.x;
    const int lane = threadIdx.x;
    __shared__ float acc[SEQ];
    __shared__ int   lst[128];
    __shared__ float skey[128];
    __shared__ unsigned mw[32];
    const float* P = g_P + (size_t)h * SEQ * SEQ;
    unsigned* MB = g_M + h * SEQ * (SEQ / 32);

    for (int j = lane; j < SEQ; j += 32) acc[j] = 0.f;
    __syncwarp();
    for (int j = lane; j < HB; j += 32) {
        float s = 0.f;
        for (int i = 0; i < HB; i++) s += P[(size_t)i * SEQ + j];
        acc[j] = s;
    }
    for (int p = lane; p < HB; p += 32) lst[p] = p;
    int cnt = HB;
    __syncwarp();

    for (int t = HB; t < SEQ; t++) {
        const float* Prow = P + (size_t)t * SEQ;
        for (int p = lane; p < cnt; p += 32) {
            const float* a = Prow + lst[p];
            asm volatile("prefetch.global.L2 [%0];" :: "l"(a));
        }
        if (lane == 0) {
            const float* a = Prow + t;
            asm volatile("prefetch.global.L2 [%0];" :: "l"(a));
        }

        for (int p = lane; p < cnt; p += 32) skey[p] = acc[lst[p]];
        __syncwarp();

        const int r = cnt - (HB - 1);
        for (int rep = 0; rep < r; rep++) {
            float bv = FLT_MAX; int bidx = -1; int bpos = 0;
            for (int p = lane; p < cnt; p += 32) {
                float v = skey[p]; int ix = lst[p];
                if (v < bv || (v == bv && ix > bidx)) { bv = v; bidx = ix; bpos = p; }
            }
#pragma unroll
            for (int o = 16; o; o >>= 1) {
                float ov = __shfl_down_sync(0xffffffffu, bv, o);
                int   oi = __shfl_down_sync(0xffffffffu, bidx, o);
                int   op = __shfl_down_sync(0xffffffffu, bpos, o);
                if (ov < bv || (ov == bv && oi > bidx)) { bv = ov; bidx = oi; bpos = op; }
            }
            bidx = __shfl_sync(0xffffffffu, bidx, 0);
            bpos = __shfl_sync(0xffffffffu, bpos, 0);
            if (bidx >= 4) {
                if (lane == 0) {
                    acc[bidx] = 0.f;
                    lst[bpos]  = lst[cnt - 1];
                    skey[bpos] = skey[cnt - 1];
                }
                cnt--;
            } else {
                if (lane == 0) skey[bpos] = FLT_MAX;
            }
            __syncwarp();
        }
        if (lane == 0) lst[cnt] = t;
        cnt++;
        mw[lane] = 0u;
        __syncwarp();
        for (int p = lane; p < cnt; p += 32) {
            int ix = lst[p];
            acc[ix] += Prow[ix];
            atomicOr(&mw[ix >> 5], 1u << (ix & 31));
        }
        __syncwarp();
        MB[t * 32 + lane] = mw[lane];
        __syncwarp();
    }
}

// ======================= masked renorm softmax + P@V (writes AO hi/lo) =======================
__global__ __launch_bounds__(128) void pv_kernel()
{
    const int s = blockIdx.x, h = blockIdx.y;
    const int tid = threadIdx.x;
    const int lane = tid & 31, wid = tid >> 5;
    __shared__ float pv[224];
    __shared__ int   pj[224];
    __shared__ int   wbase[4];
    __shared__ float wsum[4];
    __shared__ int   s_cnt;
    __shared__ float s_sum;
    const float* Prow = g_P + (size_t)h * SEQ * SEQ + (size_t)s * SEQ;
    const unsigned* mb = g_M + (h * SEQ + s) * (SEQ / 32);

    float pr[8]; bool al[8];
    int c = 0; float lsum = 0.f;
    const int j0 = tid * 8;
#pragma unroll
    for (int u = 0; u < 8; u++) {
        const int j = j0 + u;
        bool a;
        if (s < HB) a = (j <= s);
        else        a = (j <= s) && ((j + RB >= s) || ((mb[j >> 5] >> (j & 31)) & 1u));
        float val = a ? Prow[j] : 0.f;
        al[u] = a; pr[u] = val;
        if (a) { c++; lsum += val; }
    }
    int inc = c;
#pragma unroll
    for (int o = 1; o < 32; o <<= 1) {
        int v = __shfl_up_sync(0xffffffffu, inc, o);
        if (lane >= o) inc += v;
    }
    float ws = lsum;
#pragma unroll
    for (int o = 16; o; o >>= 1) ws += __shfl_xor_sync(0xffffffffu, ws, o);
    if (lane == 31) wbase[wid] = inc;
    if (lane == 0)  wsum[wid] = ws;
    __syncthreads();
    if (tid == 0) {
        int tot = 0;
#pragma unroll
        for (int w = 0; w < 4; w++) { int b = wbase[w]; wbase[w] = tot; tot += b; }
        s_cnt = tot;
        s_sum = wsum[0] + wsum[1] + wsum[2] + wsum[3];
    }
    __syncthreads();
    int k = wbase[wid] + inc - c;
#pragma unroll
    for (int u = 0; u < 8; u++)
        if (al[u]) { pv[k] = pr[u]; pj[k] = j0 + u; k++; }
    __syncthreads();

    const int cnt = s_cnt;
    const float inv = 1.0f / s_sum;
    const float* Vh = g_V + h * HD + tid;
    float acc = 0.f;
    int m2 = 0;
    for (; m2 + 4 <= cnt; m2 += 4) {
        acc += pv[m2 + 0] * Vh[(size_t)pj[m2 + 0] * DMODEL];
        acc += pv[m2 + 1] * Vh[(size_t)pj[m2 + 1] * DMODEL];
        acc += pv[m2 + 2] * Vh[(size_t)pj[m2 + 2] * DMODEL];
        acc += pv[m2 + 3] * Vh[(size_t)pj[m2 + 3] * DMODEL];
    }
    for (; m2 < cnt; m2++) acc += pv[m2] * Vh[(size_t)pj[m2] * DMODEL];

    float v = acc * inv;
    __nv_bfloat16 hv = __float2bfloat16(v);
    size_t oi = (size_t)s * DMODEL + h * HD + tid;
    g_AOhi[oi] = hv;
    g_AOlo[oi] = __float2bfloat16(v - __bfloat162float(hv));
}

// ======================= launch =======================
extern "C" void kernel_launch(void* const* d_in, const int* in_sizes, int n_in,
                              void* d_out, int out_size)
{
    const float* X  = (const float*)d_in[0];
    const float* Wq = (const float*)d_in[2];
    const float* Wk = (const float*)d_in[3];
    const float* Wv = (const float*)d_in[4];
    const float* Wo = (const float*)d_in[5];
    float* out = (float*)d_out;

    cudaFuncSetAttribute(mm_qkv_kernel, cudaFuncAttributeMaxDynamicSharedMemorySize, MM_SMEM);
    cudaFuncSetAttribute(mm_qk_kernel,  cudaFuncAttributeMaxDynamicSharedMemorySize, MM_SMEM);
    cudaFuncSetAttribute(mm_o_kernel,   cudaFuncAttributeMaxDynamicSharedMemorySize, MM_SMEM);

    cvt_all_kernel<<<(X4 + 4 * W4 + 255) / 256, 256>>>(X, Wq, Wk, Wv, Wo);
    mm_qkv_kernel<<<dim3(DMODEL / 64, SEQ / 128, 3), 256, MM_SMEM>>>();
    rope_kernel<<<dim3((SEQ * NH * 64) / 256, 2), 256>>>();
    mm_qk_kernel<<<dim3(SEQ / 64, SEQ / 128, NH), 256, MM_SMEM>>>();
    softmax_kernel<<<dim3(SEQ, NH), 256>>>();
    scan_kernel<<<NH, 32>>>();
    pv_kernel<<<dim3(SEQ, NH), 128>>>();
    mm_o_kernel<<<dim3(DMODEL / 64, SEQ / 128), 256, MM_SMEM>>>(out);
}

// round 6
// speedup vs baseline: 2.2835x; 1.3472x over previous
#include <cuda_runtime.h>
#include <cuda_bf16.h>
#include <math.h>
#include <float.h>
#include <stdint.h>

#define SEQ 1024
#define DMODEL 4096
#define NH 32
#define HD 128
#define HB 102
#define RB 102

// ======================= static device scratch =======================
__device__ __align__(256) float g_Q[SEQ * DMODEL];
__device__ __align__(256) float g_K[SEQ * DMODEL];
__device__ __align__(256) float g_V[SEQ * DMODEL];
__device__ __align__(256) float g_P[(size_t)NH * SEQ * SEQ];
__device__ unsigned g_M[NH * SEQ * (SEQ / 32)];
__device__ __align__(256) __nv_bfloat16 g_Xhi[SEQ * DMODEL], g_Xlo[SEQ * DMODEL];
__device__ __align__(256) __nv_bfloat16 g_Whi[4][DMODEL * DMODEL];
__device__ __align__(256) __nv_bfloat16 g_Wlo[4][DMODEL * DMODEL];
__device__ __align__(256) __nv_bfloat16 g_Qhi[SEQ * DMODEL], g_Qlo[SEQ * DMODEL];
__device__ __align__(256) __nv_bfloat16 g_Khi[SEQ * DMODEL], g_Klo[SEQ * DMODEL];
__device__ __align__(256) __nv_bfloat16 g_AOhi[SEQ * DMODEL], g_AOlo[SEQ * DMODEL];

// ======================= helpers =======================
__device__ __forceinline__ uint32_t smem_u32(const void* p) {
    uint32_t a;
    asm("{ .reg .u64 t; cvta.to.shared.u64 t, %1; cvt.u32.u64 %0, t; }" : "=r"(a) : "l"(p));
    return a;
}
__device__ __forceinline__ void cp16(uint32_t dst, const void* src) {
    asm volatile("cp.async.cg.shared.global [%0], [%1], 16;" :: "r"(dst), "l"(src));
}
__device__ __forceinline__ void cp_commit() { asm volatile("cp.async.commit_group;" ::: "memory"); }
__device__ __forceinline__ void cp_wait1() { asm volatile("cp.async.wait_group 1;" ::: "memory"); }
__device__ __forceinline__ void cp_wait0() { asm volatile("cp.async.wait_group 0;" ::: "memory"); }

__device__ __forceinline__ void ldsm4(uint32_t* r, uint32_t addr) {
    asm volatile("ldmatrix.sync.aligned.m8n8.x4.shared.b16 {%0,%1,%2,%3}, [%4];"
        : "=r"(r[0]), "=r"(r[1]), "=r"(r[2]), "=r"(r[3]) : "r"(addr));
}
__device__ __forceinline__ void mma_bf16(float* c, const uint32_t* a, uint32_t b0, uint32_t b1) {
    asm volatile("mma.sync.aligned.m16n8k16.row.col.f32.bf16.bf16.f32 "
        "{%0,%1,%2,%3}, {%4,%5,%6,%7}, {%8,%9}, {%0,%1,%2,%3};"
        : "+f"(c[0]), "+f"(c[1]), "+f"(c[2]), "+f"(c[3])
        : "r"(a[0]), "r"(a[1]), "r"(a[2]), "r"(a[3]), "r"(b0), "r"(b1));
}

// ======================= split-bf16 HMMA GEMM core =======================
// C[128 x 64] = (Ahi+Alo)[128 x K] * (Bhi+Blo)[64 x K]^T   (lo*lo dropped)
#define A_SLAB 16384
#define B_SLAB 8192
#define STAGE (2 * A_SLAB + 2 * B_SLAB)
#define MM_SMEM (2 * STAGE)

__device__ __forceinline__ void ld_stage(
    uint32_t st, const __nv_bfloat16* Ahi, const __nv_bfloat16* Alo,
    const __nv_bfloat16* Bhi, const __nv_bfloat16* Blo,
    int lda, int ldb, int k0, int tid)
{
#pragma unroll
    for (int it = 0; it < 4; it++) {
        int idx = it * 256 + tid;
        int row = idx >> 3, g = idx & 7;
        uint32_t off = row * 128 + ((g ^ (row & 7)) << 4);
        size_t s = (size_t)row * lda + k0 + g * 8;
        cp16(st + off, Ahi + s);
        cp16(st + A_SLAB + off, Alo + s);
    }
#pragma unroll
    for (int it = 0; it < 2; it++) {
        int idx = it * 256 + tid;
        int row = idx >> 3, g = idx & 7;
        uint32_t off = row * 128 + ((g ^ (row & 7)) << 4);
        size_t s = (size_t)row * ldb + k0 + g * 8;
        cp16(st + 2 * A_SLAB + off, Bhi + s);
        cp16(st + 2 * A_SLAB + B_SLAB + off, Blo + s);
    }
}

__device__ __forceinline__ void mm_hmma(
    const __nv_bfloat16* __restrict__ Ahi, const __nv_bfloat16* __restrict__ Alo, int lda,
    const __nv_bfloat16* __restrict__ Bhi, const __nv_bfloat16* __restrict__ Blo, int ldb,
    float* __restrict__ C, int ldc, int nk, float scale)
{
    extern __shared__ char smem[];
    const uint32_t sb = smem_u32(smem);
    const int tid = threadIdx.x, lane = tid & 31, wid = tid >> 5;
    const int wm = wid & 3, wn = wid >> 2;

    float c[2][4][4];
#pragma unroll
    for (int i = 0; i < 2; i++)
#pragma unroll
        for (int j = 0; j < 4; j++)
#pragma unroll
            for (int q = 0; q < 4; q++) c[i][j][q] = 0.f;

    ld_stage(sb, Ahi, Alo, Bhi, Blo, lda, ldb, 0, tid); cp_commit();
    ld_stage(sb + STAGE, Ahi, Alo, Bhi, Blo, lda, ldb, 64, tid); cp_commit();

    const int axor = lane & 7;
    for (int ck = 0; ck < nk; ck++) {
        if (ck == nk - 1) cp_wait0(); else cp_wait1();
        __syncthreads();
        const uint32_t st = sb + (ck & 1) * STAGE;
#pragma unroll
        for (int k16 = 0; k16 < 4; k16++) {
            uint32_t ah[2][4], al[2][4];
#pragma unroll
            for (int i = 0; i < 2; i++) {
                int arow = wm * 32 + i * 16 + (lane & 15);
                uint32_t ad = st + (uint32_t)(arow * 128)
                            + (uint32_t)(((2 * k16 + (lane >> 4)) ^ axor) << 4);
                ldsm4(ah[i], ad);
                ldsm4(al[i], ad + A_SLAB);
            }
#pragma unroll
            for (int j4 = 0; j4 < 2; j4++) {
                int brow = wn * 32 + j4 * 16 + ((lane >> 4) << 3) + (lane & 7);
                uint32_t bd = st + 2 * A_SLAB + (uint32_t)(brow * 128)
                            + (uint32_t)(((2 * k16 + ((lane >> 3) & 1)) ^ axor) << 4);
                uint32_t bh[4], bl[4];
                ldsm4(bh, bd);
                ldsm4(bl, bd + B_SLAB);
#pragma unroll
                for (int i = 0; i < 2; i++) {
                    mma_bf16(c[i][2 * j4],     ah[i], bh[0], bh[1]);
                    mma_bf16(c[i][2 * j4],     ah[i], bl[0], bl[1]);
                    mma_bf16(c[i][2 * j4],     al[i], bh[0], bh[1]);
                    mma_bf16(c[i][2 * j4 + 1], ah[i], bh[2], bh[3]);
                    mma_bf16(c[i][2 * j4 + 1], ah[i], bl[2], bl[3]);
                    mma_bf16(c[i][2 * j4 + 1], al[i], bh[2], bh[3]);
                }
            }
        }
        __syncthreads();
        if (ck + 2 < nk) {
            ld_stage(st, Ahi, Alo, Bhi, Blo, lda, ldb, (ck + 2) * 64, tid);
            cp_commit();
        }
    }

    const int r0 = wm * 32 + (lane >> 2);
    const int c0 = wn * 32 + (lane & 3) * 2;
#pragma unroll
    for (int i = 0; i < 2; i++)
#pragma unroll
        for (int j = 0; j < 4; j++) {
            float2 v0 = { c[i][j][0] * scale, c[i][j][1] * scale };
            float2 v1 = { c[i][j][2] * scale, c[i][j][3] * scale };
            *(float2*)&C[(size_t)(r0 + i * 16) * ldc + c0 + j * 8] = v0;
            *(float2*)&C[(size_t)(r0 + i * 16 + 8) * ldc + c0 + j * 8] = v1;
        }
}

// ======================= fused conversion fp32 -> bf16 hi/lo =======================
#define X4 (SEQ * DMODEL / 4)
#define W4 (DMODEL * DMODEL / 4)
__global__ __launch_bounds__(256) void cvt_all_kernel(
    const float* __restrict__ X, const float* __restrict__ Wq,
    const float* __restrict__ Wk, const float* __restrict__ Wv,
    const float* __restrict__ Wo)
{
    long long i = (long long)blockIdx.x * 256 + threadIdx.x;
    const float* src;
    __nv_bfloat16 *hi, *lo;
    long long r;
    if (i < X4)                    { src = X;  hi = g_Xhi;    lo = g_Xlo;    r = i; }
    else if ((r = i - X4) < W4)    { src = Wq; hi = g_Whi[0]; lo = g_Wlo[0]; }
    else if ((r -= W4) < W4)       { src = Wk; hi = g_Whi[1]; lo = g_Wlo[1]; }
    else if ((r -= W4) < W4)       { src = Wv; hi = g_Whi[2]; lo = g_Wlo[2]; }
    else if ((r -= W4) < W4)       { src = Wo; hi = g_Whi[3]; lo = g_Wlo[3]; }
    else return;
    float4 v = ((const float4*)src)[r];
    __nv_bfloat16 h0 = __float2bfloat16(v.x), h1 = __float2bfloat16(v.y);
    __nv_bfloat16 h2 = __float2bfloat16(v.z), h3 = __float2bfloat16(v.w);
    __nv_bfloat162 H01; H01.x = h0; H01.y = h1;
    __nv_bfloat162 H23; H23.x = h2; H23.y = h3;
    __nv_bfloat162 L01, L23;
    L01.x = __float2bfloat16(v.x - __bfloat162float(h0));
    L01.y = __float2bfloat16(v.y - __bfloat162float(h1));
    L23.x = __float2bfloat16(v.z - __bfloat162float(h2));
    L23.y = __float2bfloat16(v.w - __bfloat162float(h3));
    *(__nv_bfloat162*)(hi + 4 * (size_t)r)     = H01;
    *(__nv_bfloat162*)(hi + 4 * (size_t)r + 2) = H23;
    *(__nv_bfloat162*)(lo + 4 * (size_t)r)     = L01;
    *(__nv_bfloat162*)(lo + 4 * (size_t)r + 2) = L23;
}

// ======================= GEMM wrappers =======================
__global__ __launch_bounds__(256, 2) void mm_qkv_kernel()
{
    const int z = blockIdx.z;
    const int m0 = blockIdx.y * 128, n0 = blockIdx.x * 64;
    float* O = (z == 0) ? g_Q : (z == 1) ? g_K : g_V;
    mm_hmma(g_Xhi + (size_t)m0 * DMODEL, g_Xlo + (size_t)m0 * DMODEL, DMODEL,
            g_Whi[z] + (size_t)n0 * DMODEL, g_Wlo[z] + (size_t)n0 * DMODEL, DMODEL,
            O + (size_t)m0 * DMODEL + n0, DMODEL, DMODEL / 64, 1.0f);
}

__global__ __launch_bounds__(256, 2) void mm_o_kernel(float* __restrict__ out)
{
    const int m0 = blockIdx.y * 128, n0 = blockIdx.x * 64;
    mm_hmma(g_AOhi + (size_t)m0 * DMODEL, g_AOlo + (size_t)m0 * DMODEL, DMODEL,
            g_Whi[3] + (size_t)n0 * DMODEL, g_Wlo[3] + (size_t)n0 * DMODEL, DMODEL,
            out + (size_t)m0 * DMODEL + n0, DMODEL, DMODEL / 64, 1.0f);
}

__global__ __launch_bounds__(256, 2) void mm_qk_kernel()
{
    const int h = blockIdx.z;
    const int m0 = blockIdx.y * 128, n0 = blockIdx.x * 64;
    if (n0 > m0 + 127) return;
    mm_hmma(g_Qhi + (size_t)m0 * DMODEL + h * HD, g_Qlo + (size_t)m0 * DMODEL + h * HD, DMODEL,
            g_Khi + (size_t)n0 * DMODEL + h * HD, g_Klo + (size_t)n0 * DMODEL + h * HD, DMODEL,
            g_P + (size_t)h * SEQ * SEQ + (size_t)m0 * SEQ + n0, SEQ,
            HD / 64, 0.08838834764831845f);
}

// ======================= RoPE: fp32 Q/K -> roped bf16 hi/lo =======================
__global__ void rope_kernel()
{
    int idx = blockIdx.x * blockDim.x + threadIdx.x;
    const float* src = blockIdx.y ? g_K : g_Q;
    __nv_bfloat16* hi = blockIdx.y ? g_Khi : g_Qhi;
    __nv_bfloat16* lo = blockIdx.y ? g_Klo : g_Qlo;
    int p = idx & 63;
    int h = (idx >> 6) & 31;
    int s = idx >> 11;
    float inv = 1.0f / powf(10000.0f, (float)(2 * p) * (1.0f / 128.0f));
    float ang = (float)s * inv;
    float sn, c;
    sincosf(ang, &sn, &c);
    size_t b = (size_t)s * DMODEL + h * HD + p;
    float q0 = src[b], q1 = src[b + 64];
    float r0 = q0 * c - q1 * sn;
    float r1 = q1 * c + q0 * sn;
    __nv_bfloat16 h0 = __float2bfloat16(r0);
    __nv_bfloat16 h1 = __float2bfloat16(r1);
    hi[b] = h0;      lo[b]      = __float2bfloat16(r0 - __bfloat162float(h0));
    hi[b + 64] = h1; lo[b + 64] = __float2bfloat16(r1 - __bfloat162float(h1));
}

// ======================= softmax (probs P0, zero above diagonal) =======================
__global__ __launch_bounds__(256) void softmax_kernel()
{
    const int i = blockIdx.x, h = blockIdx.y;
    float* row = g_P + (size_t)h * SEQ * SEQ + (size_t)i * SEQ;
    const int n = i + 1;
    const int tid = threadIdx.x;
    const int lane = tid & 31, wid = tid >> 5;
    __shared__ float red[16];

    float m = -FLT_MAX;
    for (int j = tid; j < n; j += 256) m = fmaxf(m, row[j]);
#pragma unroll
    for (int o = 16; o; o >>= 1) m = fmaxf(m, __shfl_xor_sync(0xffffffffu, m, o));
    if (lane == 0) red[wid] = m;
    __syncthreads();
    m = red[0];
#pragma unroll
    for (int w = 1; w < 8; w++) m = fmaxf(m, red[w]);

    float s = 0.f;
    for (int j = tid; j < n; j += 256) s += expf(row[j] - m);
#pragma unroll
    for (int o = 16; o; o >>= 1) s += __shfl_xor_sync(0xffffffffu, s, o);
    if (lane == 0) red[8 + wid] = s;
    __syncthreads();
    float tot = 0.f;
#pragma unroll
    for (int w = 0; w < 8; w++) tot += red[8 + w];
    const float invs = 1.0f / tot;

    for (int j = tid; j < SEQ; j += 256)
        row[j] = (j < n) ? expf(row[j] - m) * invs : 0.f;
}

// ======================= H2O sequential scan =======================
// 128 threads/block: all 4 warps double-buffer-stage row t+1 into smem via
// cp.async while warp 0 runs the sequential top-k / acc-update on the staged
// row t. Removes DRAM latency from the 922-step dependency chain.
__global__ __launch_bounds__(128) void scan_kernel()
{
    const int h = blockIdx.x;
    const int tid = threadIdx.x;
    const int lane = tid & 31, wid = tid >> 5;
    __shared__ float acc[SEQ];
    __shared__ float rowbuf[2][SEQ];
    __shared__ int   lst[128];
    __shared__ float skey[128];
    __shared__ unsigned mw[32];
    const float* P = g_P + (size_t)h * SEQ * SEQ;
    unsigned* MB = g_M + h * SEQ * (SEQ / 32);

    for (int j = tid; j < SEQ; j += 128) acc[j] = 0.f;
    __syncthreads();
    // acc0[j] = sum_{i<HB} P0[i,j] for j<HB  (coalesced across threads)
    if (tid < HB) {
        float s = 0.f;
        for (int i = 0; i < HB; i++) s += P[(size_t)i * SEQ + tid];
        acc[tid] = s;
        lst[tid] = tid;
    }
    // stage row HB
    {
        uint32_t dst = smem_u32(&rowbuf[HB & 1][0]);
        const float* src = P + (size_t)HB * SEQ;
        for (int g = tid; g < SEQ / 4; g += 128) cp16(dst + g * 16, src + g * 4);
        cp_commit();
    }
    cp_wait0();
    __syncthreads();

    int cnt = HB;
    for (int t = HB; t < SEQ; t++) {
        // stage row t+1 (all threads; overlaps warp-0 compute below)
        if (t + 1 < SEQ) {
            uint32_t dst = smem_u32(&rowbuf[(t + 1) & 1][0]);
            const float* src = P + (size_t)(t + 1) * SEQ;
            for (int g = tid; g < SEQ / 4; g += 128) cp16(dst + g * 16, src + g * 4);
            cp_commit();
        }
        if (wid == 0) {
            const float* Prow = rowbuf[t & 1];
            for (int p = lane; p < cnt; p += 32) skey[p] = acc[lst[p]];
            __syncwarp();

            const int r = cnt - (HB - 1);
            for (int rep = 0; rep < r; rep++) {
                float bv = FLT_MAX; int bidx = -1; int bpos = 0;
                for (int p = lane; p < cnt; p += 32) {
                    float v = skey[p]; int ix = lst[p];
                    if (v < bv || (v == bv && ix > bidx)) { bv = v; bidx = ix; bpos = p; }
                }
#pragma unroll
                for (int o = 16; o; o >>= 1) {
                    float ov = __shfl_down_sync(0xffffffffu, bv, o);
                    int   oi = __shfl_down_sync(0xffffffffu, bidx, o);
                    int   op = __shfl_down_sync(0xffffffffu, bpos, o);
                    if (ov < bv || (ov == bv && oi > bidx)) { bv = ov; bidx = oi; bpos = op; }
                }
                bidx = __shfl_sync(0xffffffffu, bidx, 0);
                bpos = __shfl_sync(0xffffffffu, bpos, 0);
                if (bidx >= 4) {
                    if (lane == 0) {
                        acc[bidx] = 0.f;
                        lst[bpos]  = lst[cnt - 1];
                        skey[bpos] = skey[cnt - 1];
                    }
                    cnt--;
                } else {
                    if (lane == 0) skey[bpos] = FLT_MAX;
                }
                __syncwarp();
            }
            if (lane == 0) lst[cnt] = t;
            cnt++;
            mw[lane] = 0u;
            __syncwarp();
            for (int p = lane; p < cnt; p += 32) {
                int ix = lst[p];
                acc[ix] += Prow[ix];
                atomicOr(&mw[ix >> 5], 1u << (ix & 31));
            }
            __syncwarp();
            MB[t * 32 + lane] = mw[lane];
        }
        cp_wait0();
        __syncthreads();
    }
}

// ======================= masked renorm softmax + P@V (writes AO hi/lo) =======================
// 8 consecutive rows per block for the same head: allowed column sets overlap
// heavily (recent windows share 101/102, heavy sets evolve slowly) -> V row
// gathers hit L1 on reuse.
__global__ __launch_bounds__(128) void pv_kernel()
{
    const int h = blockIdx.y;
    const int tid = threadIdx.x;
    const int lane = tid & 31, wid = tid >> 5;
    __shared__ float pv[224];
    __shared__ int   pj[224];
    __shared__ int   wbase[4];
    __shared__ float wsum[4];
    __shared__ int   s_cnt;
    __shared__ float s_sum;

    for (int u8 = 0; u8 < 8; u8++) {
        const int s = blockIdx.x * 8 + u8;
        const float* Prow = g_P + (size_t)h * SEQ * SEQ + (size_t)s * SEQ;
        const unsigned* mb = g_M + (h * SEQ + s) * (SEQ / 32);

        float pr[8]; bool al[8];
        int c = 0; float lsum = 0.f;
        const int j0 = tid * 8;
#pragma unroll
        for (int u = 0; u < 8; u++) {
            const int j = j0 + u;
            bool a;
            if (s < HB) a = (j <= s);
            else        a = (j <= s) && ((j + RB >= s) || ((mb[j >> 5] >> (j & 31)) & 1u));
            float val = a ? Prow[j] : 0.f;
            al[u] = a; pr[u] = val;
            if (a) { c++; lsum += val; }
        }
        int inc = c;
#pragma unroll
        for (int o = 1; o < 32; o <<= 1) {
            int v = __shfl_up_sync(0xffffffffu, inc, o);
            if (lane >= o) inc += v;
        }
        float ws = lsum;
#pragma unroll
        for (int o = 16; o; o >>= 1) ws += __shfl_xor_sync(0xffffffffu, ws, o);
        if (lane == 31) wbase[wid] = inc;
        if (lane == 0)  wsum[wid] = ws;
        __syncthreads();
        if (tid == 0) {
            int tot = 0;
#pragma unroll
            for (int w = 0; w < 4; w++) { int b = wbase[w]; wbase[w] = tot; tot += b; }
            s_cnt = tot;
            s_sum = wsum[0] + wsum[1] + wsum[2] + wsum[3];
        }
        __syncthreads();
        int k = wbase[wid] + inc - c;
#pragma unroll
        for (int u = 0; u < 8; u++)
            if (al[u]) { pv[k] = pr[u]; pj[k] = j0 + u; k++; }
        __syncthreads();

        const int cnt = s_cnt;
        const float inv = 1.0f / s_sum;
        const float* Vh = g_V + h * HD + tid;
        float acc = 0.f;
        int m2 = 0;
        for (; m2 + 4 <= cnt; m2 += 4) {
            acc += pv[m2 + 0] * Vh[(size_t)pj[m2 + 0] * DMODEL];
            acc += pv[m2 + 1] * Vh[(size_t)pj[m2 + 1] * DMODEL];
            acc += pv[m2 + 2] * Vh[(size_t)pj[m2 + 2] * DMODEL];
            acc += pv[m2 + 3] * Vh[(size_t)pj[m2 + 3] * DMODEL];
        }
        for (; m2 < cnt; m2++) acc += pv[m2] * Vh[(size_t)pj[m2] * DMODEL];

        float v = acc * inv;
        __nv_bfloat16 hv = __float2bfloat16(v);
        size_t oi = (size_t)s * DMODEL + h * HD + tid;
        g_AOhi[oi] = hv;
        g_AOlo[oi] = __float2bfloat16(v - __bfloat162float(hv));
        __syncthreads();
    }
}

// ======================= launch =======================
extern "C" void kernel_launch(void* const* d_in, const int* in_sizes, int n_in,
                              void* d_out, int out_size)
{
    const float* X  = (const float*)d_in[0];
    const float* Wq = (const float*)d_in[2];
    const float* Wk = (const float*)d_in[3];
    const float* Wv = (const float*)d_in[4];
    const float* Wo = (const float*)d_in[5];
    float* out = (float*)d_out;

    cudaFuncSetAttribute(mm_qkv_kernel, cudaFuncAttributeMaxDynamicSharedMemorySize, MM_SMEM);
    cudaFuncSetAttribute(mm_qk_kernel,  cudaFuncAttributeMaxDynamicSharedMemorySize, MM_SMEM);
    cudaFuncSetAttribute(mm_o_kernel,   cudaFuncAttributeMaxDynamicSharedMemorySize, MM_SMEM);

    cvt_all_kernel<<<(X4 + 4 * W4 + 255) / 256, 256>>>(X, Wq, Wk, Wv, Wo);
    mm_qkv_kernel<<<dim3(DMODEL / 64, SEQ / 128, 3), 256, MM_SMEM>>>();
    rope_kernel<<<dim3((SEQ * NH * 64) / 256, 2), 256>>>();
    mm_qk_kernel<<<dim3(SEQ / 64, SEQ / 128, NH), 256, MM_SMEM>>>();
    softmax_kernel<<<dim3(SEQ, NH), 256>>>();
    scan_kernel<<<NH, 128>>>();
    pv_kernel<<<dim3(SEQ / 8, NH), 128>>>();
    mm_o_kernel<<<dim3(DMODEL / 64, SEQ / 128), 256, MM_SMEM>>>(out);
}